// round 5
// baseline (speedup 1.0000x reference)
#include <cuda_runtime.h>
#include <math.h>

typedef unsigned long long ull;
#define IMG 256

__device__ float gZ [IMG*256*64];
__device__ float gY [IMG*64*64];
__device__ float gF [IMG*64*64];
__device__ float gT [IMG*256*64];
__device__ float gW1[128*64];
__device__ float gTb[256*68];
__device__ float gTAT[66*256];
__device__ float gWB2[64*128];
__device__ float gKCP[2*32*32*32*2];
__device__ float gG  [2*32*32*32*2];

__device__ __forceinline__ ull pk(float x) {
    ull r; unsigned xi = __float_as_uint(x);
    asm("mov.b64 %0, {%1, %1};" : "=l"(r) : "r"(xi));
    return r;
}
__device__ __forceinline__ void fma2(ull& d, ull a, ull b) {
    asm("fma.rn.f32x2 %0, %1, %2, %0;" : "+l"(d) : "l"(a), "l"(b));
}
__device__ __forceinline__ float2 uf(ull v) {
    float2 f; asm("mov.b64 {%0, %1}, %2;" : "=f"(f.x), "=f"(f.y) : "l"(v));
    return f;
}
__device__ __forceinline__ int k2map(int p) { return (p < 16) ? 2 * p : 2 * (p - 16) + 1; }

__global__ void k_tables() {
    int idx = blockIdx.x * 256 + threadIdx.x;  // 69*256
    const float W0 = 6.2831853071795864769f / 256.0f;
    if (idx < 8192) {           // gW1 [w<128][c p-order]
        int w = idx >> 6, c = idx & 63;
        int k2 = k2map(c >> 1);
        float s, cc; sincosf(((k2 * w) & 255) * W0, &s, &cc);
        gW1[idx] = (c & 1) ? -s : cc;
    }
    if (idx < 256 * 68) {       // gTb [h][2t+s], t<=32
        int h = idx / 68, tr = idx % 68;
        int t = tr >> 1; float v = 0.f;
        if (t <= 32) { float s, cc; sincosf(((t * h) & 255) * W0, &s, &cc); v = (tr & 1) ? s : cc; }
        gTb[idx] = v;
    }
    if (idx < 66 * 256) {       // gTAT [k<66][h] /16
        int k = idx >> 8, h = idx & 255;
        int t = k >> 1;
        float s, cc; sincosf(((t * h) & 255) * W0, &s, &cc);
        gTAT[idx] = ((k & 1) ? s : cc) * 0.0625f;
    }
    if (idx < 8192) {           // gWB2 [kk p-order][w<128]
        int kk = idx >> 7, w = idx & 127;
        int k2 = k2map(kk >> 1);
        float s, cc; sincosf(((k2 * w) & 255) * W0, &s, &cc);
        float v;
        if ((kk & 1) == 0) v = ((k2 == 0) ? 1.0f : 2.0f) * 0.0625f * cc;
        else               v = (k2 == 0) ? 0.0f : -0.125f * s;
        gWB2[idx] = v;
    }
}

__global__ void k_pow(const float* __restrict__ kern, const float* __restrict__ rp) {
    int idx = blockIdx.x * 256 + threadIdx.x;
    float kr = kern[2 * idx], ki = kern[2 * idx + 1];
    float r = *rp, outr, outi;
    if (r == 1.0f) { outr = kr; outi = ki; }
    else {
        float m2 = kr * kr + ki * ki;
        if (m2 == 0.0f) { outr = 0.0f; outi = 0.0f; }
        else {
            float mag = expf(0.5f * r * logf(m2));
            float th = atan2f(ki, kr) * r;
            float s, c; sincosf(th, &s, &c);
            outr = mag * c; outi = mag * s;
        }
    }
    gKCP[2 * idx] = outr; gKCP[2 * idx + 1] = outi;
}

__global__ void k_g() {
    __shared__ float tw[64];
    int tid = threadIdx.x;
    if (tid < 32) {
        float s, c; sincosf(tid * (6.2831853071795864769f / 32.0f), &s, &c);
        tw[2 * tid] = c; tw[2 * tid + 1] = s;
    }
    __syncthreads();
    int bi = blockIdx.x;
    int s_ = bi >> 7, rest = bi & 127;
    int m1 = rest >> 2, dq = rest & 3;
    int d = dq * 8 + (tid >> 5), m2 = tid & 31;
    float ar = 0.f, ai = 0.f;
    #pragma unroll 8
    for (int j = 0; j < 32; j++) {
        int a = (j * d) & 31;
        float tr = tw[2 * a], ti = tw[2 * a + 1];
        int base = (((s_ * 32 + j) * 32 + m1) * 32 + m2) * 2;
        float cr = gKCP[base], ci = gKCP[base + 1];
        ar += tr * cr - ti * ci;
        ai += tr * ci + ti * cr;
    }
    int ob = (((s_ * 32 + d) * 32 + m1) * 32 + m2) * 2;
    gG[ob] = ar * 0.03125f; gG[ob + 1] = ai * 0.03125f;
}

// F1: Z[row][c] = sum_{w<128} (U|V)[row][w]*W1[w][c]  (256 thr, 2 rows x 16 cols/thread)
__global__ void __launch_bounds__(256) k_f1(const float* __restrict__ x) {
    extern __shared__ float sm[];
    float* Us = sm;                 // [128][65]
    float* Vs = sm + 128 * 65;
    float* Ws = sm + 2 * 128 * 65;  // [128][64]
    int tid = threadIdx.x;
    size_t r0 = (size_t)blockIdx.x * 128;
    for (int i = tid; i < 2048; i += 256)
        ((float4*)Ws)[i] = ((const float4*)gW1)[i];
    int ty = tid >> 2, tx = tid & 3;   // ty 0..63 (2 rows), tx 0..3 (16 cols)
    int lane = tid & 15, rg = tid >> 4;
    ull acc[2][8] = {};
    for (int kt = 0; kt < 2; kt++) {
        __syncthreads();
        #pragma unroll
        for (int rr = 0; rr < 8; rr++) {
            int row = rr * 16 + rg;
            const float* xp = x + (r0 + row) * 256 + kt * 64 + lane * 4;
            float4 a = *(const float4*)xp;
            float4 b = *(const float4*)(xp + 128);
            int o = row * 65 + lane * 4;
            Us[o] = a.x + b.x; Us[o + 1] = a.y + b.y; Us[o + 2] = a.z + b.z; Us[o + 3] = a.w + b.w;
            Vs[o] = a.x - b.x; Vs[o + 1] = a.y - b.y; Vs[o + 2] = a.z - b.z; Vs[o + 3] = a.w - b.w;
        }
        __syncthreads();
        const float* Ar = ((tx < 2) ? Us : Vs) + ty * 130;
        const float* Wk = Ws + kt * 4096 + tx * 16;
        #pragma unroll 4
        for (int k = 0; k < 64; k++) {
            float a0 = Ar[k], a1 = Ar[65 + k];
            const ulonglong2* bw = (const ulonglong2*)(Wk + k * 64);
            ulonglong2 B0 = bw[0], B1 = bw[1], B2 = bw[2], B3 = bw[3];
            ull b[8] = {B0.x, B0.y, B1.x, B1.y, B2.x, B2.y, B3.x, B3.y};
            ull p0 = pk(a0), p1 = pk(a1);
            #pragma unroll
            for (int j = 0; j < 8; j++) {
                fma2(acc[0][j], p0, b[j]);
                fma2(acc[1][j], p1, b[j]);
            }
        }
    }
    #pragma unroll
    for (int i = 0; i < 2; i++) {
        float* o = &gZ[(r0 + ty * 2 + i) * 64 + tx * 16];
        #pragma unroll
        for (int q = 0; q < 4; q++) {
            float2 v0 = uf(acc[i][2 * q]), v1 = uf(acc[i][2 * q + 1]);
            *(float4*)&o[q * 4] = make_float4(v0.x, v0.y, v1.x, v1.y);
        }
    }
}

// F2: C/S GEMM over h + conjugate-pair reconstruction
__global__ void __launch_bounds__(160) k_f2() {
    __shared__ float Zs[64 * 68];
    __shared__ float Tbs[64 * 68];
    int tid = threadIdx.x;
    int img = blockIdx.x;
    int tx = tid & 7, ty = tid >> 3;  // ty valid < 17
    ull acc[4][4] = {};
    for (int hc = 0; hc < 4; hc++) {
        __syncthreads();
        for (int i = tid; i < 1024; i += 160) {
            int row = i >> 4, q = i & 15;
            *(float4*)&Zs[row * 68 + q * 4] =
                *(const float4*)&gZ[((size_t)img * 256 + hc * 64 + row) * 64 + q * 4];
        }
        for (int i = tid; i < 64 * 17; i += 160) {
            int row = i / 17, q = i % 17;
            *(float4*)&Tbs[row * 68 + q * 4] = *(const float4*)&gTb[(hc * 64 + row) * 68 + q * 4];
        }
        __syncthreads();
        if (ty < 17) {
            #pragma unroll 2
            for (int k = 0; k < 64; k++) {
                const float* at = &Tbs[k * 68 + ty * 4];
                float a0 = at[0], a1 = at[1], a2 = at[2], a3 = at[3];
                const ulonglong2* bw = (const ulonglong2*)&Zs[k * 68 + tx * 8];
                ulonglong2 B0 = bw[0], B1 = bw[1];
                ull b[4] = {B0.x, B0.y, B1.x, B1.y};
                ull p0 = pk(a0), p1 = pk(a1), p2 = pk(a2), p3 = pk(a3);
                #pragma unroll
                for (int j = 0; j < 4; j++) {
                    fma2(acc[0][j], p0, b[j]); fma2(acc[1][j], p1, b[j]);
                    fma2(acc[2][j], p2, b[j]); fma2(acc[3][j], p3, b[j]);
                }
            }
        }
    }
    if (ty < 17) {
        #pragma unroll
        for (int j = 0; j < 2; j++) {
            int t = 2 * ty + j;
            if (t > 32) break;
            float yp[8], ym[8];
            #pragma unroll
            for (int q = 0; q < 4; q++) {
                float2 C = uf(acc[2 * j][q]), S = uf(acc[2 * j + 1][q]);
                yp[2 * q]     = (C.x + S.y) * 0.00390625f;
                yp[2 * q + 1] = (C.y - S.x) * 0.00390625f;
                ym[2 * q]     = (C.x - S.y) * 0.00390625f;
                ym[2 * q + 1] = (C.y + S.x) * 0.00390625f;
            }
            if (t < 32) {
                float* o = &gY[((size_t)img * 64 + t) * 64 + tx * 8];
                *(float4*)o = *(float4*)&yp[0]; *(float4*)&o[4] = *(float4*)&yp[4];
            }
            if (t >= 1) {
                float* o = &gY[((size_t)img * 64 + (64 - t)) * 64 + tx * 8];
                *(float4*)o = *(float4*)&ym[0]; *(float4*)&o[4] = *(float4*)&ym[4];
            }
        }
    }
}

__global__ void k_mix() {
    __shared__ float Ys[8][32][16];
    __shared__ float Gr[32][9], Gi[32][9];
    int tid = threadIdx.x;
    int bi = blockIdx.x;
    int k1i = bi >> 2, q = bi & 3;
    int s_ = (k1i < 32) ? 0 : 1;
    int m1 = k1i & 31;
    int b = tid >> 5, c = tid & 31;
    {
        const float4* ysrc = (const float4*)(gY + ((size_t)(b * 32 + c) * 64 + k1i) * 64 + q * 16);
        float4* dst = (float4*)&Ys[b][c][0];
        #pragma unroll
        for (int t = 0; t < 4; t++) dst[t] = ysrc[t];
    }
    {
        int d = tid >> 3, kq = tid & 7;
        int m2 = k2map(q * 8 + kq);
        int gi = (((s_ * 32 + d) * 32 + m1) * 32 + m2) * 2;
        Gr[d][kq] = gG[gi]; Gi[d][kq] = gG[gi + 1];
    }
    __syncthreads();
    float ar[8] = {}, ai[8] = {};
    for (int cc = 0; cc < 32; cc++) {
        int d = (c - cc) & 31;
        #pragma unroll
        for (int kq = 0; kq < 8; kq++) {
            float gr = Gr[d][kq], gim = Gi[d][kq];
            float yr = Ys[b][cc][2 * kq], yi = Ys[b][cc][2 * kq + 1];
            ar[kq] += gr * yr - gim * yi;
            ai[kq] += gr * yi + gim * yr;
        }
    }
    float* fo = gF + ((size_t)(b * 32 + c) * 64 + k1i) * 64 + q * 16;
    #pragma unroll
    for (int kq = 0; kq < 8; kq++) { fo[2 * kq] = ar[kq]; fo[2 * kq + 1] = ai[kq]; }
}

// I1: T[h][c] = sum_{k<66} gTAT[k][h] * Bp[k][c]   (grid = img x colhalf)
__global__ void __launch_bounds__(256) k_i1() {
    __shared__ float Bp[66 * 36];
    int tid = threadIdx.x;
    int bi = blockIdx.x;        // 512
    int img = bi >> 1, ch = bi & 1;
    for (int i = tid; i < 264; i += 256) {
        int t = i >> 3, q = i & 7;
        float4 fp = make_float4(0, 0, 0, 0), fm = make_float4(0, 0, 0, 0);
        if (t <= 31) fp = *(const float4*)&gF[((size_t)img * 64 + t) * 64 + ch * 32 + q * 4];
        if (t >= 1)  fm = *(const float4*)&gF[((size_t)img * 64 + (64 - t)) * 64 + ch * 32 + q * 4];
        float4 P = make_float4(fp.x + fm.x, fp.y + fm.y, fp.z + fm.z, fp.w + fm.w);
        float4 d = make_float4(fp.x - fm.x, fp.y - fm.y, fp.z - fm.z, fp.w - fm.w);
        *(float4*)&Bp[(2 * t) * 36 + q * 4]     = P;
        *(float4*)&Bp[(2 * t + 1) * 36 + q * 4] = make_float4(-d.y, d.x, -d.w, d.z);
    }
    __syncthreads();
    int ty = tid >> 2, tx = tid & 3;   // ty 0..63 (4 h-rows), tx 0..3 (8 cols)
    ull acc[4][4] = {};
    #pragma unroll 2
    for (int k = 0; k < 66; k++) {
        float4 a = *(const float4*)&gTAT[k * 256 + ty * 4];
        const ulonglong2* bw = (const ulonglong2*)&Bp[k * 36 + tx * 8];
        ulonglong2 B0 = bw[0], B1 = bw[1];
        ull b[4] = {B0.x, B0.y, B1.x, B1.y};
        ull p0 = pk(a.x), p1 = pk(a.y), p2 = pk(a.z), p3 = pk(a.w);
        #pragma unroll
        for (int j = 0; j < 4; j++) {
            fma2(acc[0][j], p0, b[j]); fma2(acc[1][j], p1, b[j]);
            fma2(acc[2][j], p2, b[j]); fma2(acc[3][j], p3, b[j]);
        }
    }
    #pragma unroll
    for (int i = 0; i < 4; i++) {
        float* o = &gT[((size_t)img * 256 + ty * 4 + i) * 64 + ch * 32 + tx * 8];
        float2 v0 = uf(acc[i][0]), v1 = uf(acc[i][1]);
        float2 v2 = uf(acc[i][2]), v3 = uf(acc[i][3]);
        *(float4*)o       = make_float4(v0.x, v0.y, v1.x, v1.y);
        *(float4*)(o + 4) = make_float4(v2.x, v2.y, v3.x, v3.y);
    }
}

// I2: y[h][w], y[h][w+128] from parity-split accumulators
__global__ void __launch_bounds__(256) k_i2(float* __restrict__ out) {
    extern __shared__ float sm[];
    float* Ts = sm;             // [128][65]
    float* Wb = sm + 128 * 65;  // [64][64]
    int tid = threadIdx.x;
    int bi = blockIdx.x;        // 1024
    size_t r0 = (size_t)(bi >> 1) * 128;
    int w0 = (bi & 1) * 64;
    {
        int lane = tid & 15, rg = tid >> 4;
        #pragma unroll
        for (int rr = 0; rr < 8; rr++) {
            int row = rr * 16 + rg;
            float4 v = *(const float4*)&gT[(r0 + row) * 64 + lane * 4];
            int o = row * 65 + lane * 4;
            Ts[o] = v.x; Ts[o + 1] = v.y; Ts[o + 2] = v.z; Ts[o + 3] = v.w;
        }
        for (int i = tid; i < 1024; i += 256) {
            int row = i >> 4, q = i & 15;
            *(float4*)&Wb[row * 64 + q * 4] = *(const float4*)&gWB2[row * 128 + w0 + q * 4];
        }
    }
    __syncthreads();
    int tx = tid & 7, ty = tid >> 3;
    ull accA[4][4] = {}, accB[4][4] = {};
    const float* Ar = Ts + ty * 260;
    #pragma unroll 4
    for (int k = 0; k < 32; k++) {
        float a0 = Ar[k], a1 = Ar[65 + k], a2 = Ar[130 + k], a3 = Ar[195 + k];
        const ulonglong2* bw = (const ulonglong2*)&Wb[k * 64 + tx * 8];
        ulonglong2 B0 = bw[0], B1 = bw[1];
        ull b[4] = {B0.x, B0.y, B1.x, B1.y};
        ull p0 = pk(a0), p1 = pk(a1), p2 = pk(a2), p3 = pk(a3);
        #pragma unroll
        for (int j = 0; j < 4; j++) {
            fma2(accA[0][j], p0, b[j]); fma2(accA[1][j], p1, b[j]);
            fma2(accA[2][j], p2, b[j]); fma2(accA[3][j], p3, b[j]);
        }
    }
    #pragma unroll 4
    for (int k = 32; k < 64; k++) {
        float a0 = Ar[k], a1 = Ar[65 + k], a2 = Ar[130 + k], a3 = Ar[195 + k];
        const ulonglong2* bw = (const ulonglong2*)&Wb[k * 64 + tx * 8];
        ulonglong2 B0 = bw[0], B1 = bw[1];
        ull b[4] = {B0.x, B0.y, B1.x, B1.y};
        ull p0 = pk(a0), p1 = pk(a1), p2 = pk(a2), p3 = pk(a3);
        #pragma unroll
        for (int j = 0; j < 4; j++) {
            fma2(accB[0][j], p0, b[j]); fma2(accB[1][j], p1, b[j]);
            fma2(accB[2][j], p2, b[j]); fma2(accB[3][j], p3, b[j]);
        }
    }
    #pragma unroll
    for (int i = 0; i < 4; i++) {
        float s[8], d8[8];
        #pragma unroll
        for (int q = 0; q < 4; q++) {
            float2 a = uf(accA[i][q]), b = uf(accB[i][q]);
            s[2 * q] = a.x + b.x;  s[2 * q + 1] = a.y + b.y;
            d8[2 * q] = a.x - b.x; d8[2 * q + 1] = a.y - b.y;
        }
        float* o = out + (r0 + ty * 4 + i) * 256 + w0 + tx * 8;
        *(float4*)o = *(float4*)&s[0]; *(float4*)(o + 4) = *(float4*)&s[4];
        *(float4*)(o + 128) = *(float4*)&d8[0]; *(float4*)(o + 132) = *(float4*)&d8[4];
    }
}

extern "C" void kernel_launch(void* const* d_in, const int* in_sizes, int n_in,
                              void* d_out, int out_size) {
    const float* x    = (const float*)d_in[0];
    const float* kern = (const float*)d_in[1];
    const float* r    = (const float*)d_in[2];
    float* out = (float*)d_out;

    cudaFuncSetAttribute(k_f1, cudaFuncAttributeMaxDynamicSharedMemorySize, 99328);
    cudaFuncSetAttribute(k_i2, cudaFuncAttributeMaxDynamicSharedMemorySize, 49664);

    k_tables<<<69, 256>>>();
    k_pow<<<256, 256>>>(kern, r);
    k_g<<<256, 256>>>();
    k_f1<<<512, 256, 99328>>>(x);
    k_f2<<<256, 160>>>();
    k_mix<<<256, 256>>>();
    k_i1<<<512, 256>>>();
    k_i2<<<1024, 256, 49664>>>(out);
}

// round 6
// speedup vs baseline: 1.1822x; 1.1822x over previous
#include <cuda_runtime.h>
#include <math.h>

typedef unsigned long long ull;
#define IMG 256

__device__ float gZ [IMG*256*64];
__device__ float gY [IMG*64*64];
__device__ float gF [IMG*64*64];
__device__ float gT [IMG*256*64];
__device__ float gW1[128*64];
__device__ float gTb[256*68];
__device__ float gTAT[66*256];
__device__ float gWB2[64*128];
__device__ float gKCP[2*32*32*32*2];
__device__ float gG  [2*32*32*32*2];

__device__ __forceinline__ ull pk(float x) {
    ull r; unsigned xi = __float_as_uint(x);
    asm("mov.b64 %0, {%1, %1};" : "=l"(r) : "r"(xi));
    return r;
}
__device__ __forceinline__ void fma2(ull& d, ull a, ull b) {
    asm("fma.rn.f32x2 %0, %1, %2, %0;" : "+l"(d) : "l"(a), "l"(b));
}
__device__ __forceinline__ float2 uf(ull v) {
    float2 f; asm("mov.b64 {%0, %1}, %2;" : "=f"(f.x), "=f"(f.y) : "l"(v));
    return f;
}
__device__ __forceinline__ int k2map(int p) { return (p < 16) ? 2 * p : 2 * (p - 16) + 1; }

__global__ void k_tables() {
    int idx = blockIdx.x * 256 + threadIdx.x;  // 69*256
    const float W0 = 6.2831853071795864769f / 256.0f;
    if (idx < 8192) {           // gW1 [w<128][c p-order]
        int w = idx >> 6, c = idx & 63;
        int k2 = k2map(c >> 1);
        float s, cc; sincosf(((k2 * w) & 255) * W0, &s, &cc);
        gW1[idx] = (c & 1) ? -s : cc;
    }
    if (idx < 256 * 68) {       // gTb [h][2t+s], t<=32
        int h = idx / 68, tr = idx % 68;
        int t = tr >> 1; float v = 0.f;
        if (t <= 32) { float s, cc; sincosf(((t * h) & 255) * W0, &s, &cc); v = (tr & 1) ? s : cc; }
        gTb[idx] = v;
    }
    if (idx < 66 * 256) {       // gTAT [k<66][h] /16
        int k = idx >> 8, h = idx & 255;
        int t = k >> 1;
        float s, cc; sincosf(((t * h) & 255) * W0, &s, &cc);
        gTAT[idx] = ((k & 1) ? s : cc) * 0.0625f;
    }
    if (idx < 8192) {           // gWB2 [kk p-order][w<128]
        int kk = idx >> 7, w = idx & 127;
        int k2 = k2map(kk >> 1);
        float s, cc; sincosf(((k2 * w) & 255) * W0, &s, &cc);
        float v;
        if ((kk & 1) == 0) v = ((k2 == 0) ? 1.0f : 2.0f) * 0.0625f * cc;
        else               v = (k2 == 0) ? 0.0f : -0.125f * s;
        gWB2[idx] = v;
    }
}

__global__ void k_pow(const float* __restrict__ kern, const float* __restrict__ rp) {
    int idx = blockIdx.x * 256 + threadIdx.x;
    float kr = kern[2 * idx], ki = kern[2 * idx + 1];
    float r = *rp, outr, outi;
    if (r == 1.0f) { outr = kr; outi = ki; }
    else {
        float m2 = kr * kr + ki * ki;
        if (m2 == 0.0f) { outr = 0.0f; outi = 0.0f; }
        else {
            float mag = expf(0.5f * r * logf(m2));
            float th = atan2f(ki, kr) * r;
            float s, c; sincosf(th, &s, &c);
            outr = mag * c; outi = mag * s;
        }
    }
    gKCP[2 * idx] = outr; gKCP[2 * idx + 1] = outi;
}

__global__ void k_g() {
    __shared__ float tw[64];
    int tid = threadIdx.x;
    if (tid < 32) {
        float s, c; sincosf(tid * (6.2831853071795864769f / 32.0f), &s, &c);
        tw[2 * tid] = c; tw[2 * tid + 1] = s;
    }
    __syncthreads();
    int bi = blockIdx.x;
    int s_ = bi >> 7, rest = bi & 127;
    int m1 = rest >> 2, dq = rest & 3;
    int d = dq * 8 + (tid >> 5), m2 = tid & 31;
    float ar = 0.f, ai = 0.f;
    #pragma unroll 8
    for (int j = 0; j < 32; j++) {
        int a = (j * d) & 31;
        float tr = tw[2 * a], ti = tw[2 * a + 1];
        int base = (((s_ * 32 + j) * 32 + m1) * 32 + m2) * 2;
        float cr = gKCP[base], ci = gKCP[base + 1];
        ar += tr * cr - ti * ci;
        ai += tr * ci + ti * cr;
    }
    int ob = (((s_ * 32 + d) * 32 + m1) * 32 + m2) * 2;
    gG[ob] = ar * 0.03125f; gG[ob + 1] = ai * 0.03125f;
}

// F1: 128 rows x 64 cols per block, K=128 in 2 chunks. A transposed in smem.
__global__ void __launch_bounds__(256) k_f1(const float* __restrict__ x) {
    extern __shared__ float sm[];
    float* Ut = sm;              // [64 k][128 row]
    float* Vt = sm + 8192;
    float* Ws = sm + 16384;      // [128 w][64 c]
    int tid = threadIdx.x;
    size_t r0 = (size_t)blockIdx.x * 128;
    for (int i = tid; i < 2048; i += 256)
        ((float4*)Ws)[i] = ((const float4*)gW1)[i];
    int ty = tid >> 3, tx = tid & 7;     // rows ty*4..+3; cols tx*4 (U) and 32+tx*4 (V)
    int srow = tid & 127, sq = tid >> 7; // staging role
    ull acc[4][4] = {};
    for (int kt = 0; kt < 2; kt++) {
        __syncthreads();
        #pragma unroll
        for (int j = 0; j < 8; j++) {
            int wq = sq * 8 + j;  // quad 0..15 within chunk
            const float* xp = x + (r0 + srow) * 256 + kt * 64 + wq * 4;
            float4 a = *(const float4*)xp;
            float4 b = *(const float4*)(xp + 128);
            int wb = wq * 4;
            Ut[(wb + 0) * 128 + srow] = a.x + b.x; Vt[(wb + 0) * 128 + srow] = a.x - b.x;
            Ut[(wb + 1) * 128 + srow] = a.y + b.y; Vt[(wb + 1) * 128 + srow] = a.y - b.y;
            Ut[(wb + 2) * 128 + srow] = a.z + b.z; Vt[(wb + 2) * 128 + srow] = a.z - b.z;
            Ut[(wb + 3) * 128 + srow] = a.w + b.w; Vt[(wb + 3) * 128 + srow] = a.w - b.w;
        }
        __syncthreads();
        const float* Wk = Ws + kt * 4096;
        #pragma unroll 2
        for (int k = 0; k < 64; k++) {
            float4 au = *(const float4*)&Ut[k * 128 + ty * 4];
            float4 av = *(const float4*)&Vt[k * 128 + ty * 4];
            ulonglong2 BU = *(const ulonglong2*)&Wk[k * 64 + tx * 4];
            ulonglong2 BV = *(const ulonglong2*)&Wk[k * 64 + 32 + tx * 4];
            ull pu0 = pk(au.x), pu1 = pk(au.y), pu2 = pk(au.z), pu3 = pk(au.w);
            ull pv0 = pk(av.x), pv1 = pk(av.y), pv2 = pk(av.z), pv3 = pk(av.w);
            fma2(acc[0][0], pu0, BU.x); fma2(acc[0][1], pu0, BU.y);
            fma2(acc[1][0], pu1, BU.x); fma2(acc[1][1], pu1, BU.y);
            fma2(acc[2][0], pu2, BU.x); fma2(acc[2][1], pu2, BU.y);
            fma2(acc[3][0], pu3, BU.x); fma2(acc[3][1], pu3, BU.y);
            fma2(acc[0][2], pv0, BV.x); fma2(acc[0][3], pv0, BV.y);
            fma2(acc[1][2], pv1, BV.x); fma2(acc[1][3], pv1, BV.y);
            fma2(acc[2][2], pv2, BV.x); fma2(acc[2][3], pv2, BV.y);
            fma2(acc[3][2], pv3, BV.x); fma2(acc[3][3], pv3, BV.y);
        }
    }
    #pragma unroll
    for (int i = 0; i < 4; i++) {
        float* o = &gZ[(r0 + ty * 4 + i) * 64];
        float2 u0 = uf(acc[i][0]), u1 = uf(acc[i][1]);
        float2 v0 = uf(acc[i][2]), v1 = uf(acc[i][3]);
        *(float4*)&o[tx * 4]      = make_float4(u0.x, u0.y, u1.x, u1.y);
        *(float4*)&o[32 + tx * 4] = make_float4(v0.x, v0.y, v1.x, v1.y);
    }
}

// F2: grid (img, colhalf). out rows 2t(cos)/2t+1(sin) per thread, reconstruct Y(+t)/Y(-t).
__global__ void __launch_bounds__(288) k_f2() {
    __shared__ float Tbs[64 * 68];
    __shared__ float Zs[64 * 32];
    int tid = threadIdx.x;
    int bi = blockIdx.x;             // 512
    int img = bi >> 1, ch = bi & 1;
    int ty = tid >> 3, tx = tid & 7;
    int tyc = (ty <= 32) ? ty : 32;
    ull acc[2][2] = {};
    for (int hc = 0; hc < 4; hc++) {
        __syncthreads();
        for (int i = tid; i < 512; i += 288) {
            int row = i >> 3, q = i & 7;
            *(float4*)&Zs[row * 32 + q * 4] =
                *(const float4*)&gZ[((size_t)img * 256 + hc * 64 + row) * 64 + ch * 32 + q * 4];
        }
        for (int i = tid; i < 1088; i += 288) {
            int row = i / 17, q = i % 17;
            *(float4*)&Tbs[row * 68 + q * 4] = *(const float4*)&gTb[(hc * 64 + row) * 68 + q * 4];
        }
        __syncthreads();
        #pragma unroll 4
        for (int k = 0; k < 64; k++) {
            float2 a = *(const float2*)&Tbs[k * 68 + tyc * 2];
            ulonglong2 B = *(const ulonglong2*)&Zs[k * 32 + tx * 4];
            ull pc = pk(a.x), ps = pk(a.y);
            fma2(acc[0][0], pc, B.x); fma2(acc[0][1], pc, B.y);
            fma2(acc[1][0], ps, B.x); fma2(acc[1][1], ps, B.y);
        }
    }
    if (ty <= 32) {
        int t = ty;
        float2 C0 = uf(acc[0][0]), C1 = uf(acc[0][1]);
        float2 S0 = uf(acc[1][0]), S1 = uf(acc[1][1]);
        const float n = 0.00390625f;
        float4 yp = make_float4((C0.x + S0.y) * n, (C0.y - S0.x) * n,
                                (C1.x + S1.y) * n, (C1.y - S1.x) * n);
        float4 ym = make_float4((C0.x - S0.y) * n, (C0.y + S0.x) * n,
                                (C1.x - S1.y) * n, (C1.y + S1.x) * n);
        int c = ch * 32 + tx * 4;
        if (t < 32) *(float4*)&gY[((size_t)img * 64 + t) * 64 + c] = yp;
        if (t >= 1) *(float4*)&gY[((size_t)img * 64 + (64 - t)) * 64 + c] = ym;
    }
}

__global__ void k_mix() {
    __shared__ float Ys[8][32][16];
    __shared__ float Gr[32][9], Gi[32][9];
    int tid = threadIdx.x;
    int bi = blockIdx.x;
    int k1i = bi >> 2, q = bi & 3;
    int s_ = (k1i < 32) ? 0 : 1;
    int m1 = k1i & 31;
    int b = tid >> 5, c = tid & 31;
    {
        const float4* ysrc = (const float4*)(gY + ((size_t)(b * 32 + c) * 64 + k1i) * 64 + q * 16);
        float4* dst = (float4*)&Ys[b][c][0];
        #pragma unroll
        for (int t = 0; t < 4; t++) dst[t] = ysrc[t];
    }
    {
        int d = tid >> 3, kq = tid & 7;
        int m2 = k2map(q * 8 + kq);
        int gi = (((s_ * 32 + d) * 32 + m1) * 32 + m2) * 2;
        Gr[d][kq] = gG[gi]; Gi[d][kq] = gG[gi + 1];
    }
    __syncthreads();
    float ar[8] = {}, ai[8] = {};
    for (int cc = 0; cc < 32; cc++) {
        int d = (c - cc) & 31;
        #pragma unroll
        for (int kq = 0; kq < 8; kq++) {
            float gr = Gr[d][kq], gim = Gi[d][kq];
            float yr = Ys[b][cc][2 * kq], yi = Ys[b][cc][2 * kq + 1];
            ar[kq] += gr * yr - gim * yi;
            ai[kq] += gr * yi + gim * yr;
        }
    }
    float* fo = gF + ((size_t)(b * 32 + c) * 64 + k1i) * 64 + q * 16;
    #pragma unroll
    for (int kq = 0; kq < 8; kq++) { fo[2 * kq] = ar[kq]; fo[2 * kq + 1] = ai[kq]; }
}

// I1: T[h][c] = sum_{k<66} gTAT[k][h] * Bp[k][c]
__global__ void __launch_bounds__(256) k_i1() {
    __shared__ float Bp[66 * 36];
    int tid = threadIdx.x;
    int bi = blockIdx.x;        // 512
    int img = bi >> 1, ch = bi & 1;
    for (int i = tid; i < 264; i += 256) {
        int t = i >> 3, q = i & 7;
        float4 fp = make_float4(0, 0, 0, 0), fm = make_float4(0, 0, 0, 0);
        if (t <= 31) fp = *(const float4*)&gF[((size_t)img * 64 + t) * 64 + ch * 32 + q * 4];
        if (t >= 1)  fm = *(const float4*)&gF[((size_t)img * 64 + (64 - t)) * 64 + ch * 32 + q * 4];
        float4 P = make_float4(fp.x + fm.x, fp.y + fm.y, fp.z + fm.z, fp.w + fm.w);
        float4 d = make_float4(fp.x - fm.x, fp.y - fm.y, fp.z - fm.z, fp.w - fm.w);
        *(float4*)&Bp[(2 * t) * 36 + q * 4]     = P;
        *(float4*)&Bp[(2 * t + 1) * 36 + q * 4] = make_float4(-d.y, d.x, -d.w, d.z);
    }
    __syncthreads();
    int ty = tid >> 2, tx = tid & 3;
    ull acc[4][4] = {};
    #pragma unroll 2
    for (int k = 0; k < 66; k++) {
        float4 a = *(const float4*)&gTAT[k * 256 + ty * 4];
        const ulonglong2* bw = (const ulonglong2*)&Bp[k * 36 + tx * 8];
        ulonglong2 B0 = bw[0], B1 = bw[1];
        ull b[4] = {B0.x, B0.y, B1.x, B1.y};
        ull p0 = pk(a.x), p1 = pk(a.y), p2 = pk(a.z), p3 = pk(a.w);
        #pragma unroll
        for (int j = 0; j < 4; j++) {
            fma2(acc[0][j], p0, b[j]); fma2(acc[1][j], p1, b[j]);
            fma2(acc[2][j], p2, b[j]); fma2(acc[3][j], p3, b[j]);
        }
    }
    #pragma unroll
    for (int i = 0; i < 4; i++) {
        float* o = &gT[((size_t)img * 256 + ty * 4 + i) * 64 + ch * 32 + tx * 8];
        float2 v0 = uf(acc[i][0]), v1 = uf(acc[i][1]);
        float2 v2 = uf(acc[i][2]), v3 = uf(acc[i][3]);
        *(float4*)o       = make_float4(v0.x, v0.y, v1.x, v1.y);
        *(float4*)(o + 4) = make_float4(v2.x, v2.y, v3.x, v3.y);
    }
}

// I2: block = 64 rows, all 256 w. K=64 split by parity (k<32: even k2, k>=32: odd).
__global__ void __launch_bounds__(256) k_i2(float* __restrict__ out) {
    __shared__ float Tt[64 * 64];   // [k][row]
    __shared__ float Wb[64 * 128];  // [k][w]
    int tid = threadIdx.x;
    size_t r0 = (size_t)blockIdx.x * 64;   // 1024 blocks
    for (int i = tid; i < 2048; i += 256)
        ((float4*)Wb)[i] = ((const float4*)gWB2)[i];
    {
        int srow = tid & 63, sq = tid >> 6;
        #pragma unroll
        for (int j = 0; j < 4; j++) {
            int kq = sq * 4 + j;
            float4 v = *(const float4*)&gT[(r0 + srow) * 64 + kq * 4];
            Tt[(kq * 4 + 0) * 64 + srow] = v.x;
            Tt[(kq * 4 + 1) * 64 + srow] = v.y;
            Tt[(kq * 4 + 2) * 64 + srow] = v.z;
            Tt[(kq * 4 + 3) * 64 + srow] = v.w;
        }
    }
    __syncthreads();
    int ty = tid >> 3, tx = tid & 7;   // rows ty*2..+1; cols w = g*32 + tx*4
    ull accA[2][8] = {}, accB[2][8] = {};
    #pragma unroll 2
    for (int k = 0; k < 32; k++) {
        float2 a = *(const float2*)&Tt[k * 64 + ty * 2];
        ull p0 = pk(a.x), p1 = pk(a.y);
        #pragma unroll
        for (int g = 0; g < 4; g++) {
            ulonglong2 B = *(const ulonglong2*)&Wb[k * 128 + g * 32 + tx * 4];
            fma2(accA[0][2 * g], p0, B.x); fma2(accA[0][2 * g + 1], p0, B.y);
            fma2(accA[1][2 * g], p1, B.x); fma2(accA[1][2 * g + 1], p1, B.y);
        }
    }
    #pragma unroll 2
    for (int k = 32; k < 64; k++) {
        float2 a = *(const float2*)&Tt[k * 64 + ty * 2];
        ull p0 = pk(a.x), p1 = pk(a.y);
        #pragma unroll
        for (int g = 0; g < 4; g++) {
            ulonglong2 B = *(const ulonglong2*)&Wb[k * 128 + g * 32 + tx * 4];
            fma2(accB[0][2 * g], p0, B.x); fma2(accB[0][2 * g + 1], p0, B.y);
            fma2(accB[1][2 * g], p1, B.x); fma2(accB[1][2 * g + 1], p1, B.y);
        }
    }
    #pragma unroll
    for (int i = 0; i < 2; i++) {
        float* o = out + (r0 + ty * 2 + i) * 256;
        #pragma unroll
        for (int g = 0; g < 4; g++) {
            float2 a0 = uf(accA[i][2 * g]), a1 = uf(accA[i][2 * g + 1]);
            float2 b0 = uf(accB[i][2 * g]), b1 = uf(accB[i][2 * g + 1]);
            int w = g * 32 + tx * 4;
            *(float4*)&o[w]       = make_float4(a0.x + b0.x, a0.y + b0.y, a1.x + b1.x, a1.y + b1.y);
            *(float4*)&o[w + 128] = make_float4(a0.x - b0.x, a0.y - b0.y, a1.x - b1.x, a1.y - b1.y);
        }
    }
}

extern "C" void kernel_launch(void* const* d_in, const int* in_sizes, int n_in,
                              void* d_out, int out_size) {
    const float* x    = (const float*)d_in[0];
    const float* kern = (const float*)d_in[1];
    const float* r    = (const float*)d_in[2];
    float* out = (float*)d_out;

    cudaFuncSetAttribute(k_f1, cudaFuncAttributeMaxDynamicSharedMemorySize, 98304);

    k_tables<<<69, 256>>>();
    k_pow<<<256, 256>>>(kern, r);
    k_g<<<256, 256>>>();
    k_f1<<<512, 256, 98304>>>(x);
    k_f2<<<512, 288>>>();
    k_mix<<<256, 256>>>();
    k_i1<<<512, 256>>>();
    k_i2<<<1024, 256>>>(out);
}

// round 7
// speedup vs baseline: 1.3175x; 1.1144x over previous
#include <cuda_runtime.h>
#include <math.h>

typedef unsigned long long ull;
#define IMG 256

__device__ float gZ [IMG*256*64];
__device__ float gY [IMG*64*64];
__device__ float gF [IMG*64*64];
__device__ float gT [IMG*256*64];
__device__ float gW1[128*64];
__device__ float gTb[256*68];
__device__ float gTAT[66*256];
__device__ float gWB2[64*128];
__device__ float gKCP[2*32*32*32*2];
__device__ float gG  [2*32*32*32*2];

__device__ __forceinline__ ull pk(float x) {
    ull r; unsigned xi = __float_as_uint(x);
    asm("mov.b64 %0, {%1, %1};" : "=l"(r) : "r"(xi));
    return r;
}
__device__ __forceinline__ void fma2(ull& d, ull a, ull b) {
    asm("fma.rn.f32x2 %0, %1, %2, %0;" : "+l"(d) : "l"(a), "l"(b));
}
__device__ __forceinline__ float2 uf(ull v) {
    float2 f; asm("mov.b64 {%0, %1}, %2;" : "=f"(f.x), "=f"(f.y) : "l"(v));
    return f;
}
__device__ __forceinline__ int k2map(int p) { return (p < 16) ? 2 * p : 2 * (p - 16) + 1; }

__global__ void k_tables() {
    int idx = blockIdx.x * 256 + threadIdx.x;  // 69*256
    const float W0 = 6.2831853071795864769f / 256.0f;
    if (idx < 8192) {           // gW1 [w<128][c p-order]
        int w = idx >> 6, c = idx & 63;
        int k2 = k2map(c >> 1);
        float s, cc; sincosf(((k2 * w) & 255) * W0, &s, &cc);
        gW1[idx] = (c & 1) ? -s : cc;
    }
    if (idx < 256 * 68) {       // gTb [h][2t+s], t<=32
        int h = idx / 68, tr = idx % 68;
        int t = tr >> 1; float v = 0.f;
        if (t <= 32) { float s, cc; sincosf(((t * h) & 255) * W0, &s, &cc); v = (tr & 1) ? s : cc; }
        gTb[idx] = v;
    }
    if (idx < 66 * 256) {       // gTAT [k<66][h] /16
        int k = idx >> 8, h = idx & 255;
        int t = k >> 1;
        float s, cc; sincosf(((t * h) & 255) * W0, &s, &cc);
        gTAT[idx] = ((k & 1) ? s : cc) * 0.0625f;
    }
    if (idx < 8192) {           // gWB2 [kk p-order][w<128]
        int kk = idx >> 7, w = idx & 127;
        int k2 = k2map(kk >> 1);
        float s, cc; sincosf(((k2 * w) & 255) * W0, &s, &cc);
        float v;
        if ((kk & 1) == 0) v = ((k2 == 0) ? 1.0f : 2.0f) * 0.0625f * cc;
        else               v = (k2 == 0) ? 0.0f : -0.125f * s;
        gWB2[idx] = v;
    }
}

__global__ void k_pow(const float* __restrict__ kern, const float* __restrict__ rp) {
    int idx = blockIdx.x * 256 + threadIdx.x;
    float kr = kern[2 * idx], ki = kern[2 * idx + 1];
    float r = *rp, outr, outi;
    if (r == 1.0f) { outr = kr; outi = ki; }
    else {
        float m2 = kr * kr + ki * ki;
        if (m2 == 0.0f) { outr = 0.0f; outi = 0.0f; }
        else {
            float mag = expf(0.5f * r * logf(m2));
            float th = atan2f(ki, kr) * r;
            float s, c; sincosf(th, &s, &c);
            outr = mag * c; outi = mag * s;
        }
    }
    gKCP[2 * idx] = outr; gKCP[2 * idx + 1] = outi;
}

__global__ void k_g() {
    __shared__ float tw[64];
    int tid = threadIdx.x;
    if (tid < 32) {
        float s, c; sincosf(tid * (6.2831853071795864769f / 32.0f), &s, &c);
        tw[2 * tid] = c; tw[2 * tid + 1] = s;
    }
    __syncthreads();
    int bi = blockIdx.x;
    int s_ = bi >> 7, rest = bi & 127;
    int m1 = rest >> 2, dq = rest & 3;
    int d = dq * 8 + (tid >> 5), m2 = tid & 31;
    float ar = 0.f, ai = 0.f;
    #pragma unroll 8
    for (int j = 0; j < 32; j++) {
        int a = (j * d) & 31;
        float tr = tw[2 * a], ti = tw[2 * a + 1];
        int base = (((s_ * 32 + j) * 32 + m1) * 32 + m2) * 2;
        float cr = gKCP[base], ci = gKCP[base + 1];
        ar += tr * cr - ti * ci;
        ai += tr * ci + ti * cr;
    }
    int ob = (((s_ * 32 + d) * 32 + m1) * 32 + m2) * 2;
    gG[ob] = ar * 0.03125f; gG[ob + 1] = ai * 0.03125f;
}

// F1: 128 rows x 64 cols per block, K=128 in 8 chunks of 16.
// Staging: coalesced LDG (8 rows x 64B per warp) + XOR-swizzled conflict-free STS.
__global__ void __launch_bounds__(256, 4) k_f1(const float* __restrict__ x) {
    __shared__ __align__(16) float Ut[16 * 128];  // [k][row^swz]
    __shared__ __align__(16) float Vt[16 * 128];
    __shared__ __align__(16) float Ws[128 * 64];  // [w][c]
    int tid = threadIdx.x;
    size_t r0 = (size_t)blockIdx.x * 128;
    for (int i = tid; i < 2048; i += 256)
        ((float4*)Ws)[i] = ((const float4*)gW1)[i];
    int ty = tid >> 3, tx = tid & 7;      // compute roles: rows ty*4..+3, cols tx*4 / 32+tx*4
    int q = tid & 3, srow = tid >> 2;     // staging roles: w-quad q, rows srow, srow+64
    ull acc[4][4] = {};
    for (int kt = 0; kt < 8; kt++) {
        __syncthreads();
        #pragma unroll
        for (int it = 0; it < 2; it++) {
            int row = srow + it * 64;
            const float* xp = x + (r0 + row) * 256 + kt * 16 + q * 4;
            float4 a = *(const float4*)xp;
            float4 b = *(const float4*)(xp + 128);
            int pr = row ^ (q << 3);      // swizzle: phys_row = row ^ (((k>>2)&3)<<3), q = k>>2
            int kb = q * 4;
            Ut[(kb + 0) * 128 + pr] = a.x + b.x; Vt[(kb + 0) * 128 + pr] = a.x - b.x;
            Ut[(kb + 1) * 128 + pr] = a.y + b.y; Vt[(kb + 1) * 128 + pr] = a.y - b.y;
            Ut[(kb + 2) * 128 + pr] = a.z + b.z; Vt[(kb + 2) * 128 + pr] = a.z - b.z;
            Ut[(kb + 3) * 128 + pr] = a.w + b.w; Vt[(kb + 3) * 128 + pr] = a.w - b.w;
        }
        __syncthreads();
        #pragma unroll 4
        for (int k = 0; k < 16; k++) {
            int sw = ((k >> 2) & 3) << 3;
            int ar_ = (ty * 4) ^ sw;
            float4 au = *(const float4*)&Ut[k * 128 + ar_];
            float4 av = *(const float4*)&Vt[k * 128 + ar_];
            const float* Wk = Ws + (kt * 16 + k) * 64;
            ulonglong2 BU = *(const ulonglong2*)&Wk[tx * 4];
            ulonglong2 BV = *(const ulonglong2*)&Wk[32 + tx * 4];
            ull pu0 = pk(au.x), pu1 = pk(au.y), pu2 = pk(au.z), pu3 = pk(au.w);
            ull pv0 = pk(av.x), pv1 = pk(av.y), pv2 = pk(av.z), pv3 = pk(av.w);
            fma2(acc[0][0], pu0, BU.x); fma2(acc[0][1], pu0, BU.y);
            fma2(acc[1][0], pu1, BU.x); fma2(acc[1][1], pu1, BU.y);
            fma2(acc[2][0], pu2, BU.x); fma2(acc[2][1], pu2, BU.y);
            fma2(acc[3][0], pu3, BU.x); fma2(acc[3][1], pu3, BU.y);
            fma2(acc[0][2], pv0, BV.x); fma2(acc[0][3], pv0, BV.y);
            fma2(acc[1][2], pv1, BV.x); fma2(acc[1][3], pv1, BV.y);
            fma2(acc[2][2], pv2, BV.x); fma2(acc[2][3], pv2, BV.y);
            fma2(acc[3][2], pv3, BV.x); fma2(acc[3][3], pv3, BV.y);
        }
    }
    #pragma unroll
    for (int i = 0; i < 4; i++) {
        float* o = &gZ[(r0 + ty * 4 + i) * 64];
        float2 u0 = uf(acc[i][0]), u1 = uf(acc[i][1]);
        float2 v0 = uf(acc[i][2]), v1 = uf(acc[i][3]);
        *(float4*)&o[tx * 4]      = make_float4(u0.x, u0.y, u1.x, u1.y);
        *(float4*)&o[32 + tx * 4] = make_float4(v0.x, v0.y, v1.x, v1.y);
    }
}

// F2: grid (img, colhalf). out rows 2t(cos)/2t+1(sin) per thread, reconstruct Y(+t)/Y(-t).
__global__ void __launch_bounds__(288) k_f2() {
    __shared__ float Tbs[64 * 68];
    __shared__ float Zs[64 * 32];
    int tid = threadIdx.x;
    int bi = blockIdx.x;             // 512
    int img = bi >> 1, ch = bi & 1;
    int ty = tid >> 3, tx = tid & 7;
    int tyc = (ty <= 32) ? ty : 32;
    ull acc[2][2] = {};
    for (int hc = 0; hc < 4; hc++) {
        __syncthreads();
        for (int i = tid; i < 512; i += 288) {
            int row = i >> 3, q = i & 7;
            *(float4*)&Zs[row * 32 + q * 4] =
                *(const float4*)&gZ[((size_t)img * 256 + hc * 64 + row) * 64 + ch * 32 + q * 4];
        }
        for (int i = tid; i < 1088; i += 288) {
            int row = i / 17, q = i % 17;
            *(float4*)&Tbs[row * 68 + q * 4] = *(const float4*)&gTb[(hc * 64 + row) * 68 + q * 4];
        }
        __syncthreads();
        #pragma unroll 4
        for (int k = 0; k < 64; k++) {
            float2 a = *(const float2*)&Tbs[k * 68 + tyc * 2];
            ulonglong2 B = *(const ulonglong2*)&Zs[k * 32 + tx * 4];
            ull pc = pk(a.x), ps = pk(a.y);
            fma2(acc[0][0], pc, B.x); fma2(acc[0][1], pc, B.y);
            fma2(acc[1][0], ps, B.x); fma2(acc[1][1], ps, B.y);
        }
    }
    if (ty <= 32) {
        int t = ty;
        float2 C0 = uf(acc[0][0]), C1 = uf(acc[0][1]);
        float2 S0 = uf(acc[1][0]), S1 = uf(acc[1][1]);
        const float n = 0.00390625f;
        float4 yp = make_float4((C0.x + S0.y) * n, (C0.y - S0.x) * n,
                                (C1.x + S1.y) * n, (C1.y - S1.x) * n);
        float4 ym = make_float4((C0.x - S0.y) * n, (C0.y + S0.x) * n,
                                (C1.x - S1.y) * n, (C1.y + S1.x) * n);
        int c = ch * 32 + tx * 4;
        if (t < 32) *(float4*)&gY[((size_t)img * 64 + t) * 64 + c] = yp;
        if (t >= 1) *(float4*)&gY[((size_t)img * 64 + (64 - t)) * 64 + c] = ym;
    }
}

__global__ void k_mix() {
    __shared__ float Ys[8][32][16];
    __shared__ float Gr[32][9], Gi[32][9];
    int tid = threadIdx.x;
    int bi = blockIdx.x;
    int k1i = bi >> 2, q = bi & 3;
    int s_ = (k1i < 32) ? 0 : 1;
    int m1 = k1i & 31;
    int b = tid >> 5, c = tid & 31;
    {
        const float4* ysrc = (const float4*)(gY + ((size_t)(b * 32 + c) * 64 + k1i) * 64 + q * 16);
        float4* dst = (float4*)&Ys[b][c][0];
        #pragma unroll
        for (int t = 0; t < 4; t++) dst[t] = ysrc[t];
    }
    {
        int d = tid >> 3, kq = tid & 7;
        int m2 = k2map(q * 8 + kq);
        int gi = (((s_ * 32 + d) * 32 + m1) * 32 + m2) * 2;
        Gr[d][kq] = gG[gi]; Gi[d][kq] = gG[gi + 1];
    }
    __syncthreads();
    float ar[8] = {}, ai[8] = {};
    for (int cc = 0; cc < 32; cc++) {
        int d = (c - cc) & 31;
        #pragma unroll
        for (int kq = 0; kq < 8; kq++) {
            float gr = Gr[d][kq], gim = Gi[d][kq];
            float yr = Ys[b][cc][2 * kq], yi = Ys[b][cc][2 * kq + 1];
            ar[kq] += gr * yr - gim * yi;
            ai[kq] += gr * yi + gim * yr;
        }
    }
    float* fo = gF + ((size_t)(b * 32 + c) * 64 + k1i) * 64 + q * 16;
    #pragma unroll
    for (int kq = 0; kq < 8; kq++) { fo[2 * kq] = ar[kq]; fo[2 * kq + 1] = ai[kq]; }
}

// I1: T[h][c] = sum_{k<66} gTAT[k][h] * Bp[k][c]
__global__ void __launch_bounds__(256) k_i1() {
    __shared__ float Bp[66 * 36];
    int tid = threadIdx.x;
    int bi = blockIdx.x;        // 512
    int img = bi >> 1, ch = bi & 1;
    for (int i = tid; i < 264; i += 256) {
        int t = i >> 3, q = i & 7;
        float4 fp = make_float4(0, 0, 0, 0), fm = make_float4(0, 0, 0, 0);
        if (t <= 31) fp = *(const float4*)&gF[((size_t)img * 64 + t) * 64 + ch * 32 + q * 4];
        if (t >= 1)  fm = *(const float4*)&gF[((size_t)img * 64 + (64 - t)) * 64 + ch * 32 + q * 4];
        float4 P = make_float4(fp.x + fm.x, fp.y + fm.y, fp.z + fm.z, fp.w + fm.w);
        float4 d = make_float4(fp.x - fm.x, fp.y - fm.y, fp.z - fm.z, fp.w - fm.w);
        *(float4*)&Bp[(2 * t) * 36 + q * 4]     = P;
        *(float4*)&Bp[(2 * t + 1) * 36 + q * 4] = make_float4(-d.y, d.x, -d.w, d.z);
    }
    __syncthreads();
    int ty = tid >> 2, tx = tid & 3;
    ull acc[4][4] = {};
    #pragma unroll 2
    for (int k = 0; k < 66; k++) {
        float4 a = *(const float4*)&gTAT[k * 256 + ty * 4];
        const ulonglong2* bw = (const ulonglong2*)&Bp[k * 36 + tx * 8];
        ulonglong2 B0 = bw[0], B1 = bw[1];
        ull b[4] = {B0.x, B0.y, B1.x, B1.y};
        ull p0 = pk(a.x), p1 = pk(a.y), p2 = pk(a.z), p3 = pk(a.w);
        #pragma unroll
        for (int j = 0; j < 4; j++) {
            fma2(acc[0][j], p0, b[j]); fma2(acc[1][j], p1, b[j]);
            fma2(acc[2][j], p2, b[j]); fma2(acc[3][j], p3, b[j]);
        }
    }
    #pragma unroll
    for (int i = 0; i < 4; i++) {
        float* o = &gT[((size_t)img * 256 + ty * 4 + i) * 64 + ch * 32 + tx * 8];
        float2 v0 = uf(acc[i][0]), v1 = uf(acc[i][1]);
        float2 v2 = uf(acc[i][2]), v3 = uf(acc[i][3]);
        *(float4*)o       = make_float4(v0.x, v0.y, v1.x, v1.y);
        *(float4*)(o + 4) = make_float4(v2.x, v2.y, v3.x, v3.y);
    }
}

// I2: block = 64 rows, all 256 w. K=64 split by parity (k<32: even k2, k>=32: odd).
__global__ void __launch_bounds__(256) k_i2(float* __restrict__ out) {
    __shared__ float Tt[64 * 64];   // [k][row]
    __shared__ float Wb[64 * 128];  // [k][w]
    int tid = threadIdx.x;
    size_t r0 = (size_t)blockIdx.x * 64;   // 1024 blocks
    for (int i = tid; i < 2048; i += 256)
        ((float4*)Wb)[i] = ((const float4*)gWB2)[i];
    {
        int srow = tid & 63, sq = tid >> 6;
        #pragma unroll
        for (int j = 0; j < 4; j++) {
            int kq = sq * 4 + j;
            float4 v = *(const float4*)&gT[(r0 + srow) * 64 + kq * 4];
            Tt[(kq * 4 + 0) * 64 + srow] = v.x;
            Tt[(kq * 4 + 1) * 64 + srow] = v.y;
            Tt[(kq * 4 + 2) * 64 + srow] = v.z;
            Tt[(kq * 4 + 3) * 64 + srow] = v.w;
        }
    }
    __syncthreads();
    int ty = tid >> 3, tx = tid & 7;   // rows ty*2..+1; cols w = g*32 + tx*4
    ull accA[2][8] = {}, accB[2][8] = {};
    #pragma unroll 2
    for (int k = 0; k < 32; k++) {
        float2 a = *(const float2*)&Tt[k * 64 + ty * 2];
        ull p0 = pk(a.x), p1 = pk(a.y);
        #pragma unroll
        for (int g = 0; g < 4; g++) {
            ulonglong2 B = *(const ulonglong2*)&Wb[k * 128 + g * 32 + tx * 4];
            fma2(accA[0][2 * g], p0, B.x); fma2(accA[0][2 * g + 1], p0, B.y);
            fma2(accA[1][2 * g], p1, B.x); fma2(accA[1][2 * g + 1], p1, B.y);
        }
    }
    #pragma unroll 2
    for (int k = 32; k < 64; k++) {
        float2 a = *(const float2*)&Tt[k * 64 + ty * 2];
        ull p0 = pk(a.x), p1 = pk(a.y);
        #pragma unroll
        for (int g = 0; g < 4; g++) {
            ulonglong2 B = *(const ulonglong2*)&Wb[k * 128 + g * 32 + tx * 4];
            fma2(accB[0][2 * g], p0, B.x); fma2(accB[0][2 * g + 1], p0, B.y);
            fma2(accB[1][2 * g], p1, B.x); fma2(accB[1][2 * g + 1], p1, B.y);
        }
    }
    #pragma unroll
    for (int i = 0; i < 2; i++) {
        float* o = out + (r0 + ty * 2 + i) * 256;
        #pragma unroll
        for (int g = 0; g < 4; g++) {
            float2 a0 = uf(accA[i][2 * g]), a1 = uf(accA[i][2 * g + 1]);
            float2 b0 = uf(accB[i][2 * g]), b1 = uf(accB[i][2 * g + 1]);
            int w = g * 32 + tx * 4;
            *(float4*)&o[w]       = make_float4(a0.x + b0.x, a0.y + b0.y, a1.x + b1.x, a1.y + b1.y);
            *(float4*)&o[w + 128] = make_float4(a0.x - b0.x, a0.y - b0.y, a1.x - b1.x, a1.y - b1.y);
        }
    }
}

extern "C" void kernel_launch(void* const* d_in, const int* in_sizes, int n_in,
                              void* d_out, int out_size) {
    const float* x    = (const float*)d_in[0];
    const float* kern = (const float*)d_in[1];
    const float* r    = (const float*)d_in[2];
    float* out = (float*)d_out;

    k_tables<<<69, 256>>>();
    k_pow<<<256, 256>>>(kern, r);
    k_g<<<256, 256>>>();
    k_f1<<<512, 256>>>(x);
    k_f2<<<512, 288>>>();
    k_mix<<<256, 256>>>();
    k_i1<<<512, 256>>>();
    k_i2<<<1024, 256>>>(out);
}

// round 8
// speedup vs baseline: 1.3345x; 1.0130x over previous
#include <cuda_runtime.h>
#include <math.h>

typedef unsigned long long ull;
#define IMG 256

__device__ float gZ [IMG*256*64];
__device__ float gY [IMG*64*64];
__device__ float gF [IMG*64*64];
__device__ float gT [IMG*256*64];
__device__ float gW1[128*64];
__device__ float gTb[256*68];
__device__ float gTAT[66*256];
__device__ float gWB2[64*128];
__device__ float gKCP[2*32*32*32*2];
__device__ float gG  [2*32*32*32*2];

__device__ __forceinline__ ull pk(float x) {
    ull r; unsigned xi = __float_as_uint(x);
    asm("mov.b64 %0, {%1, %1};" : "=l"(r) : "r"(xi));
    return r;
}
__device__ __forceinline__ void fma2(ull& d, ull a, ull b) {
    asm("fma.rn.f32x2 %0, %1, %2, %0;" : "+l"(d) : "l"(a), "l"(b));
}
__device__ __forceinline__ float2 uf(ull v) {
    float2 f; asm("mov.b64 {%0, %1}, %2;" : "=f"(f.x), "=f"(f.y) : "l"(v));
    return f;
}
__device__ __forceinline__ int k2map(int p) { return (p < 16) ? 2 * p : 2 * (p - 16) + 1; }

__global__ void k_tables() {
    int idx = blockIdx.x * 256 + threadIdx.x;  // 69*256
    const float W0 = 6.2831853071795864769f / 256.0f;
    if (idx < 8192) {           // gW1 [w<128][c p-order]
        int w = idx >> 6, c = idx & 63;
        int k2 = k2map(c >> 1);
        float s, cc; sincosf(((k2 * w) & 255) * W0, &s, &cc);
        gW1[idx] = (c & 1) ? -s : cc;
    }
    if (idx < 256 * 68) {       // gTb [h][2t+s], t<=32
        int h = idx / 68, tr = idx % 68;
        int t = tr >> 1; float v = 0.f;
        if (t <= 32) { float s, cc; sincosf(((t * h) & 255) * W0, &s, &cc); v = (tr & 1) ? s : cc; }
        gTb[idx] = v;
    }
    if (idx < 66 * 256) {       // gTAT [k<66][h] /16
        int k = idx >> 8, h = idx & 255;
        int t = k >> 1;
        float s, cc; sincosf(((t * h) & 255) * W0, &s, &cc);
        gTAT[idx] = ((k & 1) ? s : cc) * 0.0625f;
    }
    if (idx < 8192) {           // gWB2 [kk p-order][w<128]
        int kk = idx >> 7, w = idx & 127;
        int k2 = k2map(kk >> 1);
        float s, cc; sincosf(((k2 * w) & 255) * W0, &s, &cc);
        float v;
        if ((kk & 1) == 0) v = ((k2 == 0) ? 1.0f : 2.0f) * 0.0625f * cc;
        else               v = (k2 == 0) ? 0.0f : -0.125f * s;
        gWB2[idx] = v;
    }
}

__global__ void k_pow(const float* __restrict__ kern, const float* __restrict__ rp) {
    int idx = blockIdx.x * 256 + threadIdx.x;
    float kr = kern[2 * idx], ki = kern[2 * idx + 1];
    float r = *rp, outr, outi;
    if (r == 1.0f) { outr = kr; outi = ki; }
    else {
        float m2 = kr * kr + ki * ki;
        if (m2 == 0.0f) { outr = 0.0f; outi = 0.0f; }
        else {
            float mag = expf(0.5f * r * logf(m2));
            float th = atan2f(ki, kr) * r;
            float s, c; sincosf(th, &s, &c);
            outr = mag * c; outi = mag * s;
        }
    }
    gKCP[2 * idx] = outr; gKCP[2 * idx + 1] = outi;
}

__global__ void k_g() {
    __shared__ float tw[64];
    int tid = threadIdx.x;
    if (tid < 32) {
        float s, c; sincosf(tid * (6.2831853071795864769f / 32.0f), &s, &c);
        tw[2 * tid] = c; tw[2 * tid + 1] = s;
    }
    __syncthreads();
    int bi = blockIdx.x;
    int s_ = bi >> 7, rest = bi & 127;
    int m1 = rest >> 2, dq = rest & 3;
    int d = dq * 8 + (tid >> 5), m2 = tid & 31;
    float ar = 0.f, ai = 0.f;
    #pragma unroll 8
    for (int j = 0; j < 32; j++) {
        int a = (j * d) & 31;
        float tr = tw[2 * a], ti = tw[2 * a + 1];
        int base = (((s_ * 32 + j) * 32 + m1) * 32 + m2) * 2;
        float cr = gKCP[base], ci = gKCP[base + 1];
        ar += tr * cr - ti * ci;
        ai += tr * ci + ti * cr;
    }
    int ob = (((s_ * 32 + d) * 32 + m1) * 32 + m2) * 2;
    gG[ob] = ar * 0.03125f; gG[ob + 1] = ai * 0.03125f;
}

// F1: 128 rows x 64 cols per block, K=128 in 8 chunks of 16.
// Software-pipelined: LDG for chunk kt+1 issued before compute of chunk kt.
__global__ void __launch_bounds__(256) k_f1(const float* __restrict__ x) {
    __shared__ __align__(16) float Ut[16 * 128];  // [k][row^swz]
    __shared__ __align__(16) float Vt[16 * 128];
    __shared__ __align__(16) float Ws[128 * 64];  // [w][c]
    int tid = threadIdx.x;
    size_t r0 = (size_t)blockIdx.x * 128;
    for (int i = tid; i < 2048; i += 256)
        ((float4*)Ws)[i] = ((const float4*)gW1)[i];
    int ty = tid >> 3, tx = tid & 7;      // compute roles
    int q = tid & 3, srow = tid >> 2;     // staging roles
    int pr = srow ^ (q << 3), kb = q * 4; // swizzled staging targets (fixed)
    float4 pa0, pb0, pa1, pb1;            // prefetch registers
    {
        const float* xp0 = x + (r0 + srow) * 256 + q * 4;
        const float* xp1 = x + (r0 + srow + 64) * 256 + q * 4;
        pa0 = *(const float4*)xp0; pb0 = *(const float4*)(xp0 + 128);
        pa1 = *(const float4*)xp1; pb1 = *(const float4*)(xp1 + 128);
    }
    ull acc[4][4] = {};
    for (int kt = 0; kt < 8; kt++) {
        __syncthreads();   // prev compute done reading smem (and Ws ready on kt=0)
        Ut[(kb + 0) * 128 + pr] = pa0.x + pb0.x; Vt[(kb + 0) * 128 + pr] = pa0.x - pb0.x;
        Ut[(kb + 1) * 128 + pr] = pa0.y + pb0.y; Vt[(kb + 1) * 128 + pr] = pa0.y - pb0.y;
        Ut[(kb + 2) * 128 + pr] = pa0.z + pb0.z; Vt[(kb + 2) * 128 + pr] = pa0.z - pb0.z;
        Ut[(kb + 3) * 128 + pr] = pa0.w + pb0.w; Vt[(kb + 3) * 128 + pr] = pa0.w - pb0.w;
        int pr1 = (srow + 64) ^ (q << 3);
        Ut[(kb + 0) * 128 + pr1] = pa1.x + pb1.x; Vt[(kb + 0) * 128 + pr1] = pa1.x - pb1.x;
        Ut[(kb + 1) * 128 + pr1] = pa1.y + pb1.y; Vt[(kb + 1) * 128 + pr1] = pa1.y - pb1.y;
        Ut[(kb + 2) * 128 + pr1] = pa1.z + pb1.z; Vt[(kb + 2) * 128 + pr1] = pa1.z - pb1.z;
        Ut[(kb + 3) * 128 + pr1] = pa1.w + pb1.w; Vt[(kb + 3) * 128 + pr1] = pa1.w - pb1.w;
        __syncthreads();
        if (kt < 7) {      // prefetch next chunk; latency hidden by compute below
            const float* xp0 = x + (r0 + srow) * 256 + (kt + 1) * 16 + q * 4;
            const float* xp1 = x + (r0 + srow + 64) * 256 + (kt + 1) * 16 + q * 4;
            pa0 = *(const float4*)xp0; pb0 = *(const float4*)(xp0 + 128);
            pa1 = *(const float4*)xp1; pb1 = *(const float4*)(xp1 + 128);
        }
        #pragma unroll 4
        for (int k = 0; k < 16; k++) {
            int sw = ((k >> 2) & 3) << 3;
            int ar_ = (ty * 4) ^ sw;
            float4 au = *(const float4*)&Ut[k * 128 + ar_];
            float4 av = *(const float4*)&Vt[k * 128 + ar_];
            const float* Wk = Ws + (kt * 16 + k) * 64;
            ulonglong2 BU = *(const ulonglong2*)&Wk[tx * 4];
            ulonglong2 BV = *(const ulonglong2*)&Wk[32 + tx * 4];
            ull pu0 = pk(au.x), pu1 = pk(au.y), pu2 = pk(au.z), pu3 = pk(au.w);
            ull pv0 = pk(av.x), pv1 = pk(av.y), pv2 = pk(av.z), pv3 = pk(av.w);
            fma2(acc[0][0], pu0, BU.x); fma2(acc[0][1], pu0, BU.y);
            fma2(acc[1][0], pu1, BU.x); fma2(acc[1][1], pu1, BU.y);
            fma2(acc[2][0], pu2, BU.x); fma2(acc[2][1], pu2, BU.y);
            fma2(acc[3][0], pu3, BU.x); fma2(acc[3][1], pu3, BU.y);
            fma2(acc[0][2], pv0, BV.x); fma2(acc[0][3], pv0, BV.y);
            fma2(acc[1][2], pv1, BV.x); fma2(acc[1][3], pv1, BV.y);
            fma2(acc[2][2], pv2, BV.x); fma2(acc[2][3], pv2, BV.y);
            fma2(acc[3][2], pv3, BV.x); fma2(acc[3][3], pv3, BV.y);
        }
    }
    #pragma unroll
    for (int i = 0; i < 4; i++) {
        float* o = &gZ[(r0 + ty * 4 + i) * 64];
        float2 u0 = uf(acc[i][0]), u1 = uf(acc[i][1]);
        float2 v0 = uf(acc[i][2]), v1 = uf(acc[i][3]);
        *(float4*)&o[tx * 4]      = make_float4(u0.x, u0.y, u1.x, u1.y);
        *(float4*)&o[32 + tx * 4] = make_float4(v0.x, v0.y, v1.x, v1.y);
    }
}

// F2: grid (img, colhalf). out rows 2t(cos)/2t+1(sin) per thread, reconstruct Y(+t)/Y(-t).
__global__ void __launch_bounds__(288) k_f2() {
    __shared__ float Tbs[64 * 68];
    __shared__ float Zs[64 * 32];
    int tid = threadIdx.x;
    int bi = blockIdx.x;             // 512
    int img = bi >> 1, ch = bi & 1;
    int ty = tid >> 3, tx = tid & 7;
    int tyc = (ty <= 32) ? ty : 32;
    ull acc[2][2] = {};
    for (int hc = 0; hc < 4; hc++) {
        __syncthreads();
        for (int i = tid; i < 512; i += 288) {
            int row = i >> 3, q = i & 7;
            *(float4*)&Zs[row * 32 + q * 4] =
                *(const float4*)&gZ[((size_t)img * 256 + hc * 64 + row) * 64 + ch * 32 + q * 4];
        }
        for (int i = tid; i < 1088; i += 288) {
            int row = i / 17, q = i % 17;
            *(float4*)&Tbs[row * 68 + q * 4] = *(const float4*)&gTb[(hc * 64 + row) * 68 + q * 4];
        }
        __syncthreads();
        #pragma unroll 4
        for (int k = 0; k < 64; k++) {
            float2 a = *(const float2*)&Tbs[k * 68 + tyc * 2];
            ulonglong2 B = *(const ulonglong2*)&Zs[k * 32 + tx * 4];
            ull pc = pk(a.x), ps = pk(a.y);
            fma2(acc[0][0], pc, B.x); fma2(acc[0][1], pc, B.y);
            fma2(acc[1][0], ps, B.x); fma2(acc[1][1], ps, B.y);
        }
    }
    if (ty <= 32) {
        int t = ty;
        float2 C0 = uf(acc[0][0]), C1 = uf(acc[0][1]);
        float2 S0 = uf(acc[1][0]), S1 = uf(acc[1][1]);
        const float n = 0.00390625f;
        float4 yp = make_float4((C0.x + S0.y) * n, (C0.y - S0.x) * n,
                                (C1.x + S1.y) * n, (C1.y - S1.x) * n);
        float4 ym = make_float4((C0.x - S0.y) * n, (C0.y + S0.x) * n,
                                (C1.x - S1.y) * n, (C1.y + S1.x) * n);
        int c = ch * 32 + tx * 4;
        if (t < 32) *(float4*)&gY[((size_t)img * 64 + t) * 64 + c] = yp;
        if (t >= 1) *(float4*)&gY[((size_t)img * 64 + (64 - t)) * 64 + c] = ym;
    }
}

__global__ void k_mix() {
    __shared__ float Ys[8][32][16];
    __shared__ float Gr[32][9], Gi[32][9];
    int tid = threadIdx.x;
    int bi = blockIdx.x;
    int k1i = bi >> 2, q = bi & 3;
    int s_ = (k1i < 32) ? 0 : 1;
    int m1 = k1i & 31;
    int b = tid >> 5, c = tid & 31;
    {
        const float4* ysrc = (const float4*)(gY + ((size_t)(b * 32 + c) * 64 + k1i) * 64 + q * 16);
        float4* dst = (float4*)&Ys[b][c][0];
        #pragma unroll
        for (int t = 0; t < 4; t++) dst[t] = ysrc[t];
    }
    {
        int d = tid >> 3, kq = tid & 7;
        int m2 = k2map(q * 8 + kq);
        int gi = (((s_ * 32 + d) * 32 + m1) * 32 + m2) * 2;
        Gr[d][kq] = gG[gi]; Gi[d][kq] = gG[gi + 1];
    }
    __syncthreads();
    float ar[8] = {}, ai[8] = {};
    for (int cc = 0; cc < 32; cc++) {
        int d = (c - cc) & 31;
        #pragma unroll
        for (int kq = 0; kq < 8; kq++) {
            float gr = Gr[d][kq], gim = Gi[d][kq];
            float yr = Ys[b][cc][2 * kq], yi = Ys[b][cc][2 * kq + 1];
            ar[kq] += gr * yr - gim * yi;
            ai[kq] += gr * yi + gim * yr;
        }
    }
    float* fo = gF + ((size_t)(b * 32 + c) * 64 + k1i) * 64 + q * 16;
    #pragma unroll
    for (int kq = 0; kq < 8; kq++) { fo[2 * kq] = ar[kq]; fo[2 * kq + 1] = ai[kq]; }
}

// I1: T[h][c] = sum_{k<66} gTAT[k][h] * Bp[k][c]
__global__ void __launch_bounds__(256) k_i1() {
    __shared__ float Bp[66 * 36];
    int tid = threadIdx.x;
    int bi = blockIdx.x;        // 512
    int img = bi >> 1, ch = bi & 1;
    for (int i = tid; i < 264; i += 256) {
        int t = i >> 3, q = i & 7;
        float4 fp = make_float4(0, 0, 0, 0), fm = make_float4(0, 0, 0, 0);
        if (t <= 31) fp = *(const float4*)&gF[((size_t)img * 64 + t) * 64 + ch * 32 + q * 4];
        if (t >= 1)  fm = *(const float4*)&gF[((size_t)img * 64 + (64 - t)) * 64 + ch * 32 + q * 4];
        float4 P = make_float4(fp.x + fm.x, fp.y + fm.y, fp.z + fm.z, fp.w + fm.w);
        float4 d = make_float4(fp.x - fm.x, fp.y - fm.y, fp.z - fm.z, fp.w - fm.w);
        *(float4*)&Bp[(2 * t) * 36 + q * 4]     = P;
        *(float4*)&Bp[(2 * t + 1) * 36 + q * 4] = make_float4(-d.y, d.x, -d.w, d.z);
    }
    __syncthreads();
    int ty = tid >> 2, tx = tid & 3;
    ull acc[4][4] = {};
    #pragma unroll 2
    for (int k = 0; k < 66; k++) {
        float4 a = *(const float4*)&gTAT[k * 256 + ty * 4];
        const ulonglong2* bw = (const ulonglong2*)&Bp[k * 36 + tx * 8];
        ulonglong2 B0 = bw[0], B1 = bw[1];
        ull b[4] = {B0.x, B0.y, B1.x, B1.y};
        ull p0 = pk(a.x), p1 = pk(a.y), p2 = pk(a.z), p3 = pk(a.w);
        #pragma unroll
        for (int j = 0; j < 4; j++) {
            fma2(acc[0][j], p0, b[j]); fma2(acc[1][j], p1, b[j]);
            fma2(acc[2][j], p2, b[j]); fma2(acc[3][j], p3, b[j]);
        }
    }
    #pragma unroll
    for (int i = 0; i < 4; i++) {
        float* o = &gT[((size_t)img * 256 + ty * 4 + i) * 64 + ch * 32 + tx * 8];
        float2 v0 = uf(acc[i][0]), v1 = uf(acc[i][1]);
        float2 v2 = uf(acc[i][2]), v3 = uf(acc[i][3]);
        *(float4*)o       = make_float4(v0.x, v0.y, v1.x, v1.y);
        *(float4*)(o + 4) = make_float4(v2.x, v2.y, v3.x, v3.y);
    }
}

// I2: block = 64 rows, all 256 w. K=64 split by parity (k<32: even k2, k>=32: odd).
__global__ void __launch_bounds__(256) k_i2(float* __restrict__ out) {
    __shared__ float Tt[64 * 64];   // [k][row]
    __shared__ float Wb[64 * 128];  // [k][w]
    int tid = threadIdx.x;
    size_t r0 = (size_t)blockIdx.x * 64;   // 1024 blocks
    for (int i = tid; i < 2048; i += 256)
        ((float4*)Wb)[i] = ((const float4*)gWB2)[i];
    {
        int srow = tid & 63, sq = tid >> 6;
        #pragma unroll
        for (int j = 0; j < 4; j++) {
            int kq = sq * 4 + j;
            float4 v = *(const float4*)&gT[(r0 + srow) * 64 + kq * 4];
            Tt[(kq * 4 + 0) * 64 + srow] = v.x;
            Tt[(kq * 4 + 1) * 64 + srow] = v.y;
            Tt[(kq * 4 + 2) * 64 + srow] = v.z;
            Tt[(kq * 4 + 3) * 64 + srow] = v.w;
        }
    }
    __syncthreads();
    int ty = tid >> 3, tx = tid & 7;   // rows ty*2..+1; cols w = g*32 + tx*4
    ull accA[2][8] = {}, accB[2][8] = {};
    #pragma unroll 2
    for (int k = 0; k < 32; k++) {
        float2 a = *(const float2*)&Tt[k * 64 + ty * 2];
        ull p0 = pk(a.x), p1 = pk(a.y);
        #pragma unroll
        for (int g = 0; g < 4; g++) {
            ulonglong2 B = *(const ulonglong2*)&Wb[k * 128 + g * 32 + tx * 4];
            fma2(accA[0][2 * g], p0, B.x); fma2(accA[0][2 * g + 1], p0, B.y);
            fma2(accA[1][2 * g], p1, B.x); fma2(accA[1][2 * g + 1], p1, B.y);
        }
    }
    #pragma unroll 2
    for (int k = 32; k < 64; k++) {
        float2 a = *(const float2*)&Tt[k * 64 + ty * 2];
        ull p0 = pk(a.x), p1 = pk(a.y);
        #pragma unroll
        for (int g = 0; g < 4; g++) {
            ulonglong2 B = *(const ulonglong2*)&Wb[k * 128 + g * 32 + tx * 4];
            fma2(accB[0][2 * g], p0, B.x); fma2(accB[0][2 * g + 1], p0, B.y);
            fma2(accB[1][2 * g], p1, B.x); fma2(accB[1][2 * g + 1], p1, B.y);
        }
    }
    #pragma unroll
    for (int i = 0; i < 2; i++) {
        float* o = out + (r0 + ty * 2 + i) * 256;
        #pragma unroll
        for (int g = 0; g < 4; g++) {
            float2 a0 = uf(accA[i][2 * g]), a1 = uf(accA[i][2 * g + 1]);
            float2 b0 = uf(accB[i][2 * g]), b1 = uf(accB[i][2 * g + 1]);
            int w = g * 32 + tx * 4;
            *(float4*)&o[w]       = make_float4(a0.x + b0.x, a0.y + b0.y, a1.x + b1.x, a1.y + b1.y);
            *(float4*)&o[w + 128] = make_float4(a0.x - b0.x, a0.y - b0.y, a1.x - b1.x, a1.y - b1.y);
        }
    }
}

extern "C" void kernel_launch(void* const* d_in, const int* in_sizes, int n_in,
                              void* d_out, int out_size) {
    const float* x    = (const float*)d_in[0];
    const float* kern = (const float*)d_in[1];
    const float* r    = (const float*)d_in[2];
    float* out = (float*)d_out;

    k_tables<<<69, 256>>>();
    k_pow<<<256, 256>>>(kern, r);
    k_g<<<256, 256>>>();
    k_f1<<<512, 256>>>(x);
    k_f2<<<512, 288>>>();
    k_mix<<<256, 256>>>();
    k_i1<<<512, 256>>>();
    k_i2<<<1024, 256>>>(out);
}

// round 9
// speedup vs baseline: 1.3613x; 1.0200x over previous
#include <cuda_runtime.h>
#include <math.h>

typedef unsigned long long ull;
#define IMG 256

__device__ float gZ [IMG*256*64];
__device__ float gY [IMG*64*64];
__device__ float gF [IMG*64*64];
__device__ float gT [IMG*256*64];
__device__ float gW1[128*64];
__device__ float gTb[256*68];
__device__ float gTAT[66*256];
__device__ float gWB2[64*128];
__device__ float gKCP[2*32*32*32*2];
__device__ float gG  [2*32*32*32*2];

__device__ __forceinline__ ull pk(float x) {
    ull r; unsigned xi = __float_as_uint(x);
    asm("mov.b64 %0, {%1, %1};" : "=l"(r) : "r"(xi));
    return r;
}
__device__ __forceinline__ void fma2(ull& d, ull a, ull b) {
    asm("fma.rn.f32x2 %0, %1, %2, %0;" : "+l"(d) : "l"(a), "l"(b));
}
__device__ __forceinline__ float2 uf(ull v) {
    float2 f; asm("mov.b64 {%0, %1}, %2;" : "=f"(f.x), "=f"(f.y) : "l"(v));
    return f;
}
__device__ __forceinline__ int k2map(int p) { return (p < 16) ? 2 * p : 2 * (p - 16) + 1; }

__global__ void k_tables() {
    int idx = blockIdx.x * 256 + threadIdx.x;  // 69*256
    const float W0 = 6.2831853071795864769f / 256.0f;
    if (idx < 8192) {           // gW1 [w<128][c p-order]
        int w = idx >> 6, c = idx & 63;
        int k2 = k2map(c >> 1);
        float s, cc; sincosf(((k2 * w) & 255) * W0, &s, &cc);
        gW1[idx] = (c & 1) ? -s : cc;
    }
    if (idx < 256 * 68) {       // gTb [h][2t+s], t<=32
        int h = idx / 68, tr = idx % 68;
        int t = tr >> 1; float v = 0.f;
        if (t <= 32) { float s, cc; sincosf(((t * h) & 255) * W0, &s, &cc); v = (tr & 1) ? s : cc; }
        gTb[idx] = v;
    }
    if (idx < 66 * 256) {       // gTAT [k<66][h] /16
        int k = idx >> 8, h = idx & 255;
        int t = k >> 1;
        float s, cc; sincosf(((t * h) & 255) * W0, &s, &cc);
        gTAT[idx] = ((k & 1) ? s : cc) * 0.0625f;
    }
    if (idx < 8192) {           // gWB2 [kk p-order][w<128]
        int kk = idx >> 7, w = idx & 127;
        int k2 = k2map(kk >> 1);
        float s, cc; sincosf(((k2 * w) & 255) * W0, &s, &cc);
        float v;
        if ((kk & 1) == 0) v = ((k2 == 0) ? 1.0f : 2.0f) * 0.0625f * cc;
        else               v = (k2 == 0) ? 0.0f : -0.125f * s;
        gWB2[idx] = v;
    }
}

__global__ void k_pow(const float* __restrict__ kern, const float* __restrict__ rp) {
    int idx = blockIdx.x * 256 + threadIdx.x;
    float kr = kern[2 * idx], ki = kern[2 * idx + 1];
    float r = *rp, outr, outi;
    if (r == 1.0f) { outr = kr; outi = ki; }
    else {
        float m2 = kr * kr + ki * ki;
        if (m2 == 0.0f) { outr = 0.0f; outi = 0.0f; }
        else {
            float mag = expf(0.5f * r * logf(m2));
            float th = atan2f(ki, kr) * r;
            float s, c; sincosf(th, &s, &c);
            outr = mag * c; outi = mag * s;
        }
    }
    gKCP[2 * idx] = outr; gKCP[2 * idx + 1] = outi;
}

__global__ void k_g() {
    __shared__ float tw[64];
    int tid = threadIdx.x;
    if (tid < 32) {
        float s, c; sincosf(tid * (6.2831853071795864769f / 32.0f), &s, &c);
        tw[2 * tid] = c; tw[2 * tid + 1] = s;
    }
    __syncthreads();
    int bi = blockIdx.x;
    int s_ = bi >> 7, rest = bi & 127;
    int m1 = rest >> 2, dq = rest & 3;
    int d = dq * 8 + (tid >> 5), m2 = tid & 31;
    float ar = 0.f, ai = 0.f;
    #pragma unroll 8
    for (int j = 0; j < 32; j++) {
        int a = (j * d) & 31;
        float tr = tw[2 * a], ti = tw[2 * a + 1];
        int base = (((s_ * 32 + j) * 32 + m1) * 32 + m2) * 2;
        float cr = gKCP[base], ci = gKCP[base + 1];
        ar += tr * cr - ti * ci;
        ai += tr * ci + ti * cr;
    }
    int ob = (((s_ * 32 + d) * 32 + m1) * 32 + m2) * 2;
    gG[ob] = ar * 0.03125f; gG[ob + 1] = ai * 0.03125f;
}

// F1: 128 rows x 64 cols per block, K=128 in 8 chunks of 16.
// Double-buffered smem + register prefetch: ONE barrier per chunk.
__global__ void __launch_bounds__(256, 3) k_f1(const float* __restrict__ x) {
    __shared__ __align__(16) float Ut[2][16 * 128];  // [buf][k][row^swz]
    __shared__ __align__(16) float Vt[2][16 * 128];
    __shared__ __align__(16) float Ws[128 * 64];     // [w][c]
    int tid = threadIdx.x;
    size_t r0 = (size_t)blockIdx.x * 128;
    for (int i = tid; i < 2048; i += 256)
        ((float4*)Ws)[i] = ((const float4*)gW1)[i];
    int ty = tid >> 3, tx = tid & 7;      // compute roles
    int q = tid & 3, srow = tid >> 2;     // staging roles
    int pr0 = srow ^ (q << 3), pr1 = (srow + 64) ^ (q << 3), kb = q * 4;
    float4 pa0, pb0, pa1, pb1;            // prefetch registers
    {
        const float* xp0 = x + (r0 + srow) * 256 + q * 4;
        const float* xp1 = x + (r0 + srow + 64) * 256 + q * 4;
        pa0 = *(const float4*)xp0; pb0 = *(const float4*)(xp0 + 128);
        pa1 = *(const float4*)xp1; pb1 = *(const float4*)(xp1 + 128);
    }
    ull acc[4][4] = {};
    for (int kt = 0; kt < 8; kt++) {
        int b = kt & 1;
        float* U = Ut[b]; float* V = Vt[b];
        U[(kb + 0) * 128 + pr0] = pa0.x + pb0.x; V[(kb + 0) * 128 + pr0] = pa0.x - pb0.x;
        U[(kb + 1) * 128 + pr0] = pa0.y + pb0.y; V[(kb + 1) * 128 + pr0] = pa0.y - pb0.y;
        U[(kb + 2) * 128 + pr0] = pa0.z + pb0.z; V[(kb + 2) * 128 + pr0] = pa0.z - pb0.z;
        U[(kb + 3) * 128 + pr0] = pa0.w + pb0.w; V[(kb + 3) * 128 + pr0] = pa0.w - pb0.w;
        U[(kb + 0) * 128 + pr1] = pa1.x + pb1.x; V[(kb + 0) * 128 + pr1] = pa1.x - pb1.x;
        U[(kb + 1) * 128 + pr1] = pa1.y + pb1.y; V[(kb + 1) * 128 + pr1] = pa1.y - pb1.y;
        U[(kb + 2) * 128 + pr1] = pa1.z + pb1.z; V[(kb + 2) * 128 + pr1] = pa1.z - pb1.z;
        U[(kb + 3) * 128 + pr1] = pa1.w + pb1.w; V[(kb + 3) * 128 + pr1] = pa1.w - pb1.w;
        __syncthreads();
        if (kt < 7) {      // prefetch next chunk; latency hidden by compute below
            const float* xp0 = x + (r0 + srow) * 256 + (kt + 1) * 16 + q * 4;
            const float* xp1 = x + (r0 + srow + 64) * 256 + (kt + 1) * 16 + q * 4;
            pa0 = *(const float4*)xp0; pb0 = *(const float4*)(xp0 + 128);
            pa1 = *(const float4*)xp1; pb1 = *(const float4*)(xp1 + 128);
        }
        #pragma unroll 4
        for (int k = 0; k < 16; k++) {
            int sw = ((k >> 2) & 3) << 3;
            int ar_ = (ty * 4) ^ sw;
            float4 au = *(const float4*)&U[k * 128 + ar_];
            float4 av = *(const float4*)&V[k * 128 + ar_];
            const float* Wk = Ws + (kt * 16 + k) * 64;
            ulonglong2 BU = *(const ulonglong2*)&Wk[tx * 4];
            ulonglong2 BV = *(const ulonglong2*)&Wk[32 + tx * 4];
            ull pu0 = pk(au.x), pu1 = pk(au.y), pu2 = pk(au.z), pu3 = pk(au.w);
            ull pv0 = pk(av.x), pv1 = pk(av.y), pv2 = pk(av.z), pv3 = pk(av.w);
            fma2(acc[0][0], pu0, BU.x); fma2(acc[0][1], pu0, BU.y);
            fma2(acc[1][0], pu1, BU.x); fma2(acc[1][1], pu1, BU.y);
            fma2(acc[2][0], pu2, BU.x); fma2(acc[2][1], pu2, BU.y);
            fma2(acc[3][0], pu3, BU.x); fma2(acc[3][1], pu3, BU.y);
            fma2(acc[0][2], pv0, BV.x); fma2(acc[0][3], pv0, BV.y);
            fma2(acc[1][2], pv1, BV.x); fma2(acc[1][3], pv1, BV.y);
            fma2(acc[2][2], pv2, BV.x); fma2(acc[2][3], pv2, BV.y);
            fma2(acc[3][2], pv3, BV.x); fma2(acc[3][3], pv3, BV.y);
        }
    }
    #pragma unroll
    for (int i = 0; i < 4; i++) {
        float* o = &gZ[(r0 + ty * 4 + i) * 64];
        float2 u0 = uf(acc[i][0]), u1 = uf(acc[i][1]);
        float2 v0 = uf(acc[i][2]), v1 = uf(acc[i][3]);
        *(float4*)&o[tx * 4]      = make_float4(u0.x, u0.y, u1.x, u1.y);
        *(float4*)&o[32 + tx * 4] = make_float4(v0.x, v0.y, v1.x, v1.y);
    }
}

// F2: grid (img, colhalf). out rows 2t(cos)/2t+1(sin) per thread, reconstruct Y(+t)/Y(-t).
__global__ void __launch_bounds__(288) k_f2() {
    __shared__ float Tbs[64 * 68];
    __shared__ float Zs[64 * 32];
    int tid = threadIdx.x;
    int bi = blockIdx.x;             // 512
    int img = bi >> 1, ch = bi & 1;
    int ty = tid >> 3, tx = tid & 7;
    int tyc = (ty <= 32) ? ty : 32;
    ull acc[2][2] = {};
    for (int hc = 0; hc < 4; hc++) {
        __syncthreads();
        for (int i = tid; i < 512; i += 288) {
            int row = i >> 3, q = i & 7;
            *(float4*)&Zs[row * 32 + q * 4] =
                *(const float4*)&gZ[((size_t)img * 256 + hc * 64 + row) * 64 + ch * 32 + q * 4];
        }
        for (int i = tid; i < 1088; i += 288) {
            int row = i / 17, q = i % 17;
            *(float4*)&Tbs[row * 68 + q * 4] = *(const float4*)&gTb[(hc * 64 + row) * 68 + q * 4];
        }
        __syncthreads();
        #pragma unroll 4
        for (int k = 0; k < 64; k++) {
            float2 a = *(const float2*)&Tbs[k * 68 + tyc * 2];
            ulonglong2 B = *(const ulonglong2*)&Zs[k * 32 + tx * 4];
            ull pc = pk(a.x), ps = pk(a.y);
            fma2(acc[0][0], pc, B.x); fma2(acc[0][1], pc, B.y);
            fma2(acc[1][0], ps, B.x); fma2(acc[1][1], ps, B.y);
        }
    }
    if (ty <= 32) {
        int t = ty;
        float2 C0 = uf(acc[0][0]), C1 = uf(acc[0][1]);
        float2 S0 = uf(acc[1][0]), S1 = uf(acc[1][1]);
        const float n = 0.00390625f;
        float4 yp = make_float4((C0.x + S0.y) * n, (C0.y - S0.x) * n,
                                (C1.x + S1.y) * n, (C1.y - S1.x) * n);
        float4 ym = make_float4((C0.x - S0.y) * n, (C0.y + S0.x) * n,
                                (C1.x - S1.y) * n, (C1.y + S1.x) * n);
        int c = ch * 32 + tx * 4;
        if (t < 32) *(float4*)&gY[((size_t)img * 64 + t) * 64 + c] = yp;
        if (t >= 1) *(float4*)&gY[((size_t)img * 64 + (64 - t)) * 64 + c] = ym;
    }
}

__global__ void k_mix() {
    __shared__ float Ys[8][32][16];
    __shared__ float Gr[32][9], Gi[32][9];
    int tid = threadIdx.x;
    int bi = blockIdx.x;
    int k1i = bi >> 2, q = bi & 3;
    int s_ = (k1i < 32) ? 0 : 1;
    int m1 = k1i & 31;
    int b = tid >> 5, c = tid & 31;
    {
        const float4* ysrc = (const float4*)(gY + ((size_t)(b * 32 + c) * 64 + k1i) * 64 + q * 16);
        float4* dst = (float4*)&Ys[b][c][0];
        #pragma unroll
        for (int t = 0; t < 4; t++) dst[t] = ysrc[t];
    }
    {
        int d = tid >> 3, kq = tid & 7;
        int m2 = k2map(q * 8 + kq);
        int gi = (((s_ * 32 + d) * 32 + m1) * 32 + m2) * 2;
        Gr[d][kq] = gG[gi]; Gi[d][kq] = gG[gi + 1];
    }
    __syncthreads();
    float ar[8] = {}, ai[8] = {};
    for (int cc = 0; cc < 32; cc++) {
        int d = (c - cc) & 31;
        #pragma unroll
        for (int kq = 0; kq < 8; kq++) {
            float gr = Gr[d][kq], gim = Gi[d][kq];
            float yr = Ys[b][cc][2 * kq], yi = Ys[b][cc][2 * kq + 1];
            ar[kq] += gr * yr - gim * yi;
            ai[kq] += gr * yi + gim * yr;
        }
    }
    float* fo = gF + ((size_t)(b * 32 + c) * 64 + k1i) * 64 + q * 16;
    #pragma unroll
    for (int kq = 0; kq < 8; kq++) { fo[2 * kq] = ar[kq]; fo[2 * kq + 1] = ai[kq]; }
}

// I1: T[h][c] = sum_{k<66} gTAT[k][h] * Bp[k][c]
__global__ void __launch_bounds__(256) k_i1() {
    __shared__ float Bp[66 * 36];
    int tid = threadIdx.x;
    int bi = blockIdx.x;        // 512
    int img = bi >> 1, ch = bi & 1;
    for (int i = tid; i < 264; i += 256) {
        int t = i >> 3, q = i & 7;
        float4 fp = make_float4(0, 0, 0, 0), fm = make_float4(0, 0, 0, 0);
        if (t <= 31) fp = *(const float4*)&gF[((size_t)img * 64 + t) * 64 + ch * 32 + q * 4];
        if (t >= 1)  fm = *(const float4*)&gF[((size_t)img * 64 + (64 - t)) * 64 + ch * 32 + q * 4];
        float4 P = make_float4(fp.x + fm.x, fp.y + fm.y, fp.z + fm.z, fp.w + fm.w);
        float4 d = make_float4(fp.x - fm.x, fp.y - fm.y, fp.z - fm.z, fp.w - fm.w);
        *(float4*)&Bp[(2 * t) * 36 + q * 4]     = P;
        *(float4*)&Bp[(2 * t + 1) * 36 + q * 4] = make_float4(-d.y, d.x, -d.w, d.z);
    }
    __syncthreads();
    int ty = tid >> 2, tx = tid & 3;
    ull acc[4][4] = {};
    #pragma unroll 2
    for (int k = 0; k < 66; k++) {
        float4 a = *(const float4*)&gTAT[k * 256 + ty * 4];
        const ulonglong2* bw = (const ulonglong2*)&Bp[k * 36 + tx * 8];
        ulonglong2 B0 = bw[0], B1 = bw[1];
        ull b[4] = {B0.x, B0.y, B1.x, B1.y};
        ull p0 = pk(a.x), p1 = pk(a.y), p2 = pk(a.z), p3 = pk(a.w);
        #pragma unroll
        for (int j = 0; j < 4; j++) {
            fma2(acc[0][j], p0, b[j]); fma2(acc[1][j], p1, b[j]);
            fma2(acc[2][j], p2, b[j]); fma2(acc[3][j], p3, b[j]);
        }
    }
    #pragma unroll
    for (int i = 0; i < 4; i++) {
        float* o = &gT[((size_t)img * 256 + ty * 4 + i) * 64 + ch * 32 + tx * 8];
        float2 v0 = uf(acc[i][0]), v1 = uf(acc[i][1]);
        float2 v2 = uf(acc[i][2]), v3 = uf(acc[i][3]);
        *(float4*)o       = make_float4(v0.x, v0.y, v1.x, v1.y);
        *(float4*)(o + 4) = make_float4(v2.x, v2.y, v3.x, v3.y);
    }
}

// I2: block = 64 rows, all 256 w. Coalesced staging + XOR-swizzled transpose.
__global__ void __launch_bounds__(256) k_i2(float* __restrict__ out) {
    __shared__ float Tt[64 * 64];   // [k][row ^ 2*(k>>2)]
    __shared__ float Wb[64 * 128];  // [k][w]
    int tid = threadIdx.x;
    size_t r0 = (size_t)blockIdx.x * 64;   // 1024 blocks
    for (int i = tid; i < 2048; i += 256)
        ((float4*)Wb)[i] = ((const float4*)gWB2)[i];
    {
        int q = tid & 15, srow = tid >> 4;  // q: k-quad, srow: 16 rows/pass
        #pragma unroll
        for (int it = 0; it < 4; it++) {
            int row = it * 16 + srow;
            float4 v = *(const float4*)&gT[(r0 + row) * 64 + q * 4];
            int pc = row ^ (2 * q);
            Tt[(q * 4 + 0) * 64 + pc] = v.x;
            Tt[(q * 4 + 1) * 64 + pc] = v.y;
            Tt[(q * 4 + 2) * 64 + pc] = v.z;
            Tt[(q * 4 + 3) * 64 + pc] = v.w;
        }
    }
    __syncthreads();
    int ty = tid >> 3, tx = tid & 7;   // rows ty*2..+1; cols w = g*32 + tx*4
    ull accA[2][8] = {}, accB[2][8] = {};
    #pragma unroll 2
    for (int k = 0; k < 32; k++) {
        float2 a = *(const float2*)&Tt[k * 64 + ((ty * 2) ^ (2 * (k >> 2)))];
        ull p0 = pk(a.x), p1 = pk(a.y);
        #pragma unroll
        for (int g = 0; g < 4; g++) {
            ulonglong2 B = *(const ulonglong2*)&Wb[k * 128 + g * 32 + tx * 4];
            fma2(accA[0][2 * g], p0, B.x); fma2(accA[0][2 * g + 1], p0, B.y);
            fma2(accA[1][2 * g], p1, B.x); fma2(accA[1][2 * g + 1], p1, B.y);
        }
    }
    #pragma unroll 2
    for (int k = 32; k < 64; k++) {
        float2 a = *(const float2*)&Tt[k * 64 + ((ty * 2) ^ (2 * (k >> 2)))];
        ull p0 = pk(a.x), p1 = pk(a.y);
        #pragma unroll
        for (int g = 0; g < 4; g++) {
            ulonglong2 B = *(const ulonglong2*)&Wb[k * 128 + g * 32 + tx * 4];
            fma2(accB[0][2 * g], p0, B.x); fma2(accB[0][2 * g + 1], p0, B.y);
            fma2(accB[1][2 * g], p1, B.x); fma2(accB[1][2 * g + 1], p1, B.y);
        }
    }
    #pragma unroll
    for (int i = 0; i < 2; i++) {
        float* o = out + (r0 + ty * 2 + i) * 256;
        #pragma unroll
        for (int g = 0; g < 4; g++) {
            float2 a0 = uf(accA[i][2 * g]), a1 = uf(accA[i][2 * g + 1]);
            float2 b0 = uf(accB[i][2 * g]), b1 = uf(accB[i][2 * g + 1]);
            int w = g * 32 + tx * 4;
            *(float4*)&o[w]       = make_float4(a0.x + b0.x, a0.y + b0.y, a1.x + b1.x, a1.y + b1.y);
            *(float4*)&o[w + 128] = make_float4(a0.x - b0.x, a0.y - b0.y, a1.x - b1.x, a1.y - b1.y);
        }
    }
}

extern "C" void kernel_launch(void* const* d_in, const int* in_sizes, int n_in,
                              void* d_out, int out_size) {
    const float* x    = (const float*)d_in[0];
    const float* kern = (const float*)d_in[1];
    const float* r    = (const float*)d_in[2];
    float* out = (float*)d_out;

    k_tables<<<69, 256>>>();
    k_pow<<<256, 256>>>(kern, r);
    k_g<<<256, 256>>>();
    k_f1<<<512, 256>>>(x);
    k_f2<<<512, 288>>>();
    k_mix<<<256, 256>>>();
    k_i1<<<512, 256>>>();
    k_i2<<<1024, 256>>>(out);
}